// round 1
// baseline (speedup 1.0000x reference)
#include <cuda_runtime.h>
#include <math.h>

#define NU 4096
#define NI 4096
#define NN 8192
#define D  128
#define KNN 10
#define PPRK 20
#define MAXDEG 256
#define DELTA 0.15f
#define ONEM  0.85f

// ---------- static device scratch (no allocations allowed) ----------
__device__ float g_xn[(size_t)NN * D];          // normalized features (users then items)
__device__ float g_sim[(size_t)NU * NI];        // sim matrix / masked PPR scores (reused)
__device__ float g_piA[(size_t)NN * NU];        // piT ping
__device__ float g_piB[(size_t)NN * NU];        // piT pong
__device__ int   g_uitems[NU * MAXDEG];
__device__ int   g_iusers[NI * MAXDEG];
__device__ int   g_ucnt[NU];
__device__ int   g_icnt[NI];
__device__ float g_invdeg[NN];
__device__ float g_dinv[NN];

// ---------- 1. row-normalize features ----------
__global__ void normalize_kernel(const float* __restrict__ fu, const float* __restrict__ fi) {
    int row = blockIdx.x;
    int t = threadIdx.x; // 128 threads
    const float* src = (row < NU) ? &fu[(size_t)row * D] : &fi[(size_t)(row - NU) * D];
    float v = src[t];
    float s = v * v;
    #pragma unroll
    for (int o = 16; o; o >>= 1) s += __shfl_xor_sync(0xffffffff, s, o);
    __shared__ float ws[4];
    if ((t & 31) == 0) ws[t >> 5] = s;
    __syncthreads();
    float tot = ws[0] + ws[1] + ws[2] + ws[3];
    g_xn[(size_t)row * D + t] = v / fmaxf(sqrtf(tot), 1e-12f);
}

// ---------- 2. sim = Xn Xn^T (fp32 tiled), 64x64 tile, BK=32 ----------
__global__ void syrk_kernel(int base) {
    __shared__ float As[32][65];  // [k][m], padded
    __shared__ float Bs[32][65];
    int tid = threadIdx.x;
    int tx = tid & 15, ty = tid >> 4;
    int bm = blockIdx.y * 64, bn = blockIdx.x * 64;
    const float* X = g_xn + (size_t)base * D;
    float acc[4][4] = {};
    for (int k0 = 0; k0 < D; k0 += 32) {
        #pragma unroll
        for (int l = 0; l < 2; ++l) {
            int idx = tid + l * 256;
            int rrow = idx >> 3;
            int rcol = (idx & 7) * 4;
            float4 a = *(const float4*)&X[(size_t)(bm + rrow) * D + k0 + rcol];
            float4 b = *(const float4*)&X[(size_t)(bn + rrow) * D + k0 + rcol];
            As[rcol + 0][rrow] = a.x; As[rcol + 1][rrow] = a.y;
            As[rcol + 2][rrow] = a.z; As[rcol + 3][rrow] = a.w;
            Bs[rcol + 0][rrow] = b.x; Bs[rcol + 1][rrow] = b.y;
            Bs[rcol + 2][rrow] = b.z; Bs[rcol + 3][rrow] = b.w;
        }
        __syncthreads();
        #pragma unroll
        for (int k = 0; k < 32; ++k) {
            float a[4], b[4];
            #pragma unroll
            for (int i = 0; i < 4; ++i) a[i] = As[k][ty * 4 + i];
            #pragma unroll
            for (int j = 0; j < 4; ++j) b[j] = Bs[k][tx * 4 + j];
            #pragma unroll
            for (int i = 0; i < 4; ++i)
                #pragma unroll
                for (int j = 0; j < 4; ++j) acc[i][j] = fmaf(a[i], b[j], acc[i][j]);
        }
        __syncthreads();
    }
    #pragma unroll
    for (int i = 0; i < 4; ++i) {
        float4 o = make_float4(acc[i][0], acc[i][1], acc[i][2], acc[i][3]);
        *(float4*)&g_sim[(size_t)(bm + ty * 4 + i) * NI + bn + tx * 4] = o;
    }
}

// ---------- 3. per-row top-K of sim -> symmetric KNN edges via atomicMax ----------
__global__ void knn_topk_kernel(float* __restrict__ adj, int base) {
    int row = blockIdx.x, t = threadIdx.x;
    __shared__ float sv[NI];
    __shared__ float rv[256];
    __shared__ int   ri[256];
    const float* srow = g_sim + (size_t)row * NI;
    for (int c = t; c < NI; c += 256) sv[c] = srow[c];
    __syncthreads();
    if (t == 0) sv[row] = -INFINITY;  // exclude diagonal
    __syncthreads();
    for (int itk = 0; itk < KNN; ++itk) {
        float bv = -INFINITY; int bi = 0;
        for (int c = t; c < NI; c += 256) {
            float v = sv[c];
            if (v > bv) { bv = v; bi = c; }
        }
        rv[t] = bv; ri[t] = bi;
        __syncthreads();
        for (int s = 128; s; s >>= 1) {
            if (t < s && rv[t + s] > rv[t]) { rv[t] = rv[t + s]; ri[t] = ri[t + s]; }
            __syncthreads();
        }
        if (t == 0) {
            int j = ri[0]; float v = rv[0];
            sv[j] = -INFINITY;
            float w = fminf(fmaxf((v + 1.0f) * 0.5f, 1e-6f), 1.0f);
            // positive floats: int-bit atomicMax == float max (init 0)
            atomicMax((int*)&adj[(size_t)(base + row) * NN + (base + j)], __float_as_int(w));
            atomicMax((int*)&adj[(size_t)(base + j) * NN + (base + row)], __float_as_int(w));
        }
        __syncthreads();
    }
}

// ---------- 4. bipartite adjacency lists ----------
__global__ void zero_counts_kernel() {
    int i = blockIdx.x * 256 + threadIdx.x;
    if (i < NU) g_ucnt[i] = 0;
    if (i < NI) g_icnt[i] = 0;
}

__global__ void build_lists_kernel(const float* __restrict__ r) {
    int u = blockIdx.x, t = threadIdx.x;
    __shared__ int scnt;
    if (t == 0) scnt = 0;
    __syncthreads();
    for (int c = t; c < NI; c += 256) {
        if (r[(size_t)u * NI + c] > 0.0f) {
            int p = atomicAdd(&scnt, 1);
            if (p < MAXDEG) g_uitems[u * MAXDEG + p] = c;
            int q = atomicAdd(&g_icnt[c], 1);
            if (q < MAXDEG) g_iusers[c * MAXDEG + q] = u;
        }
    }
    __syncthreads();
    if (t == 0) g_ucnt[u] = scnt;
}

__global__ void invdeg_kernel() {
    int j = blockIdx.x * 256 + threadIdx.x;
    if (j < NN) {
        int c = (j < NU) ? g_ucnt[j] : g_icnt[j - NU];
        g_invdeg[j] = 1.0f / (float)(c + 1);  // +1 for the self loop in A+I
    }
}

// ---------- 5. pi init (piT layout: [n][nu]) ----------
__global__ void init_pi_kernel() {
    size_t i = (size_t)blockIdx.x * 256 + threadIdx.x;
    size_t j = i / NU, u = i - j * NU;
    g_piA[i] = (j == u) ? 1.0f : 0.0f;
}

// ---------- 6. one PPR step: piT_out = 0.85 * P^T piT + 0.15 * pi0T ----------
// column j of P has nnz: diag(j) + bipartite neighbors of j. float4 over u.
__global__ void ppr_step_kernel(int flip) {
    const float* __restrict__ pin = flip ? g_piB : g_piA;
    float* __restrict__ pout      = flip ? g_piA : g_piB;
    int j = blockIdx.x;
    int t = threadIdx.x;
    int u4 = blockIdx.y * 1024 + t * 4;

    __shared__ int   L;
    __shared__ int   nbr[MAXDEG];
    __shared__ float nw[MAXDEG];
    if (t == 0) {
        int c = (j < NU) ? g_ucnt[j] : g_icnt[j - NU];
        L = min(c, MAXDEG);
    }
    __syncthreads();
    int Ll = L;
    if (j < NU) {
        for (int l = t; l < Ll; l += 256) nbr[l] = NU + g_uitems[j * MAXDEG + l];
    } else {
        for (int l = t; l < Ll; l += 256) nbr[l] = g_iusers[(j - NU) * MAXDEG + l];
    }
    __syncthreads();
    for (int l = t; l < Ll; l += 256) nw[l] = g_invdeg[nbr[l]];
    __syncthreads();

    float dj = g_invdeg[j];
    float4 p = *(const float4*)&pin[(size_t)j * NU + u4];
    float4 acc = make_float4(p.x * dj, p.y * dj, p.z * dj, p.w * dj);
    for (int l = 0; l < Ll; ++l) {
        float w = nw[l];
        float4 q = *(const float4*)&pin[(size_t)nbr[l] * NU + u4];
        acc.x = fmaf(q.x, w, acc.x);
        acc.y = fmaf(q.y, w, acc.y);
        acc.z = fmaf(q.z, w, acc.z);
        acc.w = fmaf(q.w, w, acc.w);
    }
    float4 res;
    res.x = ONEM * acc.x + ((j == u4 + 0) ? DELTA : 0.0f);
    res.y = ONEM * acc.y + ((j == u4 + 1) ? DELTA : 0.0f);
    res.z = ONEM * acc.z + ((j == u4 + 2) ? DELTA : 0.0f);
    res.w = ONEM * acc.w + ((j == u4 + 3) ? DELTA : 0.0f);
    *(float4*)&pout[(size_t)j * NU + u4] = res;
}

// ---------- 7. masked scores, transposed into g_sim[u][it] ----------
__global__ void scores_kernel(const float* __restrict__ r) {
    __shared__ float tile[32][33];
    int it0 = blockIdx.x * 32, u0 = blockIdx.y * 32;
    int tx = threadIdx.x, ty = threadIdx.y;
    tile[ty][tx] = g_piB[(size_t)(NU + it0 + ty) * NU + u0 + tx];
    __syncthreads();
    int u = u0 + ty, it = it0 + tx;
    float sc = tile[tx][ty];
    float rv = r[(size_t)u * NI + it];
    g_sim[(size_t)u * NI + it] = (rv > 0.0f) ? -INFINITY : sc;
}

// ---------- 8. copy r_train into UI and IU blocks ----------
__global__ void copy_r_kernel(const float* __restrict__ r, float* __restrict__ adj) {
    __shared__ float tile[32][33];
    int it0 = blockIdx.x * 32, u0 = blockIdx.y * 32;
    int tx = threadIdx.x, ty = threadIdx.y;
    float v = r[(size_t)(u0 + ty) * NI + it0 + tx];
    adj[(size_t)(u0 + ty) * NN + NU + it0 + tx] = v;
    tile[ty][tx] = v;
    __syncthreads();
    adj[(size_t)(NU + it0 + ty) * NN + u0 + tx] = tile[tx][ty];
}

// ---------- 9. PPR top-K extra edges ----------
__global__ void ppr_topk_kernel(float* __restrict__ adj) {
    int u = blockIdx.x, t = threadIdx.x;
    __shared__ float sv[NI];
    __shared__ float rv[256];
    __shared__ int   ri[256];
    __shared__ float selv[PPRK];
    __shared__ int   seli[PPRK];
    for (int c = t; c < NI; c += 256) sv[c] = g_sim[(size_t)u * NI + c];
    __syncthreads();
    for (int itk = 0; itk < PPRK; ++itk) {
        float bv = -INFINITY; int bi = 0;
        for (int c = t; c < NI; c += 256) {
            float v = sv[c];
            if (v > bv) { bv = v; bi = c; }
        }
        rv[t] = bv; ri[t] = bi;
        __syncthreads();
        for (int s = 128; s; s >>= 1) {
            if (t < s && rv[t + s] > rv[t]) { rv[t] = rv[t + s]; ri[t] = ri[t + s]; }
            __syncthreads();
        }
        if (t == 0) { selv[itk] = rv[0]; seli[itk] = ri[0]; sv[ri[0]] = -INFINITY; }
        __syncthreads();
    }
    if (t < PPRK) {
        float w  = fmaxf(selv[t], 0.0f);
        float mx = fmaxf(selv[0], 0.0f);  // selv[0] is the global row max
        if (mx > 0.0f) w = w / fmaxf(mx, 1e-12f);
        int it = seli[t];
        // selected positions have r_train == 0 (masked), so plain stores
        adj[(size_t)u * NN + NU + it] = w;
        adj[(size_t)(NU + it) * NN + u] = w;
    }
}

// ---------- 10. symmetric normalization ----------
__global__ void rowsum_kernel(const float* __restrict__ adj) {
    int i = blockIdx.x, t = threadIdx.x;
    const float* row = adj + (size_t)i * NN;
    float s = 0.0f;
    for (int c = t; c < NN; c += 256) s += row[c];
    __shared__ float sm[256];
    sm[t] = s;
    __syncthreads();
    for (int o = 128; o; o >>= 1) {
        if (t < o) sm[t] += sm[t + o];
        __syncthreads();
    }
    if (t == 0) {
        float rs = sm[0];
        g_dinv[i] = (rs > 0.0f) ? rsqrtf(fmaxf(rs, 1e-12f)) : 0.0f;
    }
}

__global__ void scale_kernel(float* __restrict__ adj) {
    size_t idx = ((size_t)blockIdx.x * 256 + threadIdx.x) * 4;
    size_t i = idx / NN, j = idx - i * NN;
    float di = g_dinv[i];
    float4 v = *(float4*)&adj[idx];
    v.x *= di * g_dinv[j + 0];
    v.y *= di * g_dinv[j + 1];
    v.z *= di * g_dinv[j + 2];
    v.w *= di * g_dinv[j + 3];
    *(float4*)&adj[idx] = v;
}

// ---------- launch ----------
extern "C" void kernel_launch(void* const* d_in, const int* in_sizes, int n_in,
                              void* d_out, int out_size) {
    const float* fu = (const float*)d_in[0];
    const float* fi = (const float*)d_in[1];
    const float* r  = (const float*)d_in[2];
    float* out = (float*)d_out;

    cudaMemsetAsync(out, 0, (size_t)NN * NN * sizeof(float));

    normalize_kernel<<<NN, 128>>>(fu, fi);

    dim3 g64(64, 64);
    syrk_kernel<<<g64, 256>>>(0);
    knn_topk_kernel<<<NU, 256>>>(out, 0);
    syrk_kernel<<<g64, 256>>>(NU);
    knn_topk_kernel<<<NI, 256>>>(out, NU);

    zero_counts_kernel<<<16, 256>>>();
    build_lists_kernel<<<NU, 256>>>(r);
    invdeg_kernel<<<32, 256>>>();

    init_pi_kernel<<<(int)(((size_t)NN * NU) / 256), 256>>>();
    dim3 gp(NN, 4);
    for (int s = 0; s < 5; ++s) ppr_step_kernel<<<gp, 256>>>(s & 1);

    dim3 t32(32, 32);
    dim3 g128(NI / 32, NU / 32);
    scores_kernel<<<g128, t32>>>(r);
    copy_r_kernel<<<g128, t32>>>(r, out);
    ppr_topk_kernel<<<NU, 256>>>(out);

    rowsum_kernel<<<NN, 256>>>(out);
    scale_kernel<<<(int)(((size_t)NN * NN) / 1024), 256>>>(out);
}

// round 3
// speedup vs baseline: 1.0724x; 1.0724x over previous
#include <cuda_runtime.h>
#include <math.h>

#define NU 4096
#define NI 4096
#define NN 8192
#define D  128
#define KNN 10
#define PPRK 20
#define MAXDEG 256
#define DELTA 0.15f
#define ONEM  0.85f

// ---------- static device scratch ----------
__device__ float g_xn[(size_t)NN * D];
__device__ float g_sim[(size_t)NU * NI];     // sim matrix / masked PPR scores (reused)
__device__ float g_piA[(size_t)NN * NU];     // piT ping
__device__ float g_piB[(size_t)NN * NU];     // piT pong
__device__ int   g_uitems[NU * MAXDEG];
__device__ int   g_iusers[NI * MAXDEG];
__device__ int   g_ucnt[NU];
__device__ int   g_icnt[NI];
__device__ float g_invdeg[NN];
__device__ float g_dinv[NN];

// ---------- zero the UU and II quadrants of adj ----------
__global__ void zero_quad_kernel(float* __restrict__ adj) {
    int row = blockIdx.x;
    size_t base = (size_t)row * NN + ((row < NU) ? 0 : NU);
    float4 z = make_float4(0.f, 0.f, 0.f, 0.f);
    float4* p = (float4*)&adj[base];
    #pragma unroll
    for (int i = threadIdx.x; i < NU / 4; i += 256) p[i] = z;
}

// ---------- row-normalize features ----------
__global__ void normalize_kernel(const float* __restrict__ fu, const float* __restrict__ fi) {
    int row = blockIdx.x;
    int t = threadIdx.x; // 128 threads
    const float* src = (row < NU) ? &fu[(size_t)row * D] : &fi[(size_t)(row - NU) * D];
    float v = src[t];
    float s = v * v;
    #pragma unroll
    for (int o = 16; o; o >>= 1) s += __shfl_xor_sync(0xffffffff, s, o);
    __shared__ float ws[4];
    if ((t & 31) == 0) ws[t >> 5] = s;
    __syncthreads();
    float tot = ws[0] + ws[1] + ws[2] + ws[3];
    g_xn[(size_t)row * D + t] = v / fmaxf(sqrtf(tot), 1e-12f);
}

// ---------- SYRK: sim = Xn Xn^T, 128x128 tile, 8x8 microtile, triangular ----------
__global__ void __launch_bounds__(256) syrk_kernel(int base) {
    int bm = blockIdx.y * 128, bn = blockIdx.x * 128;
    if (bn < bm) return;  // symmetry: only upper blocks
    __shared__ float As[16][132];
    __shared__ float Bs[16][132];
    int tid = threadIdx.x;
    int tx = tid & 15, ty = tid >> 4;
    const float* X = g_xn + (size_t)base * D;
    float acc[8][8] = {};
    for (int k0 = 0; k0 < D; k0 += 16) {
        #pragma unroll
        for (int l = 0; l < 2; ++l) {
            int idx = tid * 2 + l;        // 0..511
            int r   = idx >> 2;           // 0..127
            int c4  = (idx & 3) * 4;      // 0,4,8,12
            float4 a = *(const float4*)&X[(size_t)(bm + r) * D + k0 + c4];
            As[c4 + 0][r] = a.x; As[c4 + 1][r] = a.y;
            As[c4 + 2][r] = a.z; As[c4 + 3][r] = a.w;
            float4 b = *(const float4*)&X[(size_t)(bn + r) * D + k0 + c4];
            Bs[c4 + 0][r] = b.x; Bs[c4 + 1][r] = b.y;
            Bs[c4 + 2][r] = b.z; Bs[c4 + 3][r] = b.w;
        }
        __syncthreads();
        #pragma unroll
        for (int k = 0; k < 16; ++k) {
            float a[8], b[8];
            *(float4*)&a[0] = *(const float4*)&As[k][ty * 8];
            *(float4*)&a[4] = *(const float4*)&As[k][ty * 8 + 4];
            *(float4*)&b[0] = *(const float4*)&Bs[k][tx * 8];
            *(float4*)&b[4] = *(const float4*)&Bs[k][tx * 8 + 4];
            #pragma unroll
            for (int i = 0; i < 8; ++i)
                #pragma unroll
                for (int j = 0; j < 8; ++j) acc[i][j] = fmaf(a[i], b[j], acc[i][j]);
        }
        __syncthreads();
    }
    #pragma unroll
    for (int i = 0; i < 8; ++i) {
        size_t ro = (size_t)(bm + ty * 8 + i) * NI + bn + tx * 8;
        *(float4*)&g_sim[ro]     = make_float4(acc[i][0], acc[i][1], acc[i][2], acc[i][3]);
        *(float4*)&g_sim[ro + 4] = make_float4(acc[i][4], acc[i][5], acc[i][6], acc[i][7]);
    }
    if (bm != bn) {
        #pragma unroll
        for (int j = 0; j < 8; ++j) {
            size_t ro = (size_t)(bn + tx * 8 + j) * NI + bm + ty * 8;
            *(float4*)&g_sim[ro]     = make_float4(acc[0][j], acc[1][j], acc[2][j], acc[3][j]);
            *(float4*)&g_sim[ro + 4] = make_float4(acc[4][j], acc[5][j], acc[6][j], acc[7][j]);
        }
    }
}

// ---------- register-resident top-K for KNN ----------
__global__ void __launch_bounds__(256) knn_topk_kernel(float* __restrict__ adj, int base) {
    int row = blockIdx.x, t = threadIdx.x;
    float v[16];
    const float* srow = g_sim + (size_t)row * NI;
    #pragma unroll
    for (int p = 0; p < 16; ++p) {
        int c = t + p * 256;
        float x = srow[c];
        v[p] = (c == row) ? -INFINITY : x;
    }
    __shared__ float swv[8];
    __shared__ int   swi[8];
    __shared__ int   bsel;
    for (int k = 0; k < KNN; ++k) {
        float bv = v[0]; int bp = 0;
        #pragma unroll
        for (int p = 1; p < 16; ++p) if (v[p] > bv) { bv = v[p]; bp = p; }
        int bc = t + bp * 256;
        #pragma unroll
        for (int o = 16; o; o >>= 1) {
            float ov = __shfl_xor_sync(0xffffffff, bv, o);
            int   oc = __shfl_xor_sync(0xffffffff, bc, o);
            if (ov > bv || (ov == bv && oc < bc)) { bv = ov; bc = oc; }
        }
        if ((t & 31) == 0) { swv[t >> 5] = bv; swi[t >> 5] = bc; }
        __syncthreads();
        if (t == 0) {
            float BV = swv[0]; int BC = swi[0];
            #pragma unroll
            for (int w = 1; w < 8; ++w)
                if (swv[w] > BV || (swv[w] == BV && swi[w] < BC)) { BV = swv[w]; BC = swi[w]; }
            bsel = BC;
            float wgt = fminf(fmaxf((BV + 1.0f) * 0.5f, 1e-6f), 1.0f);
            atomicMax((int*)&adj[(size_t)(base + row) * NN + (base + BC)], __float_as_int(wgt));
            atomicMax((int*)&adj[(size_t)(base + BC) * NN + (base + row)], __float_as_int(wgt));
        }
        __syncthreads();
        int sc = bsel;
        if ((sc & 255) == t) v[sc >> 8] = -INFINITY;
    }
}

// ---------- bipartite adjacency lists ----------
__global__ void zero_counts_kernel() {
    int i = blockIdx.x * 256 + threadIdx.x;
    if (i < NU) g_ucnt[i] = 0;
    if (i < NI) g_icnt[i] = 0;
}

__global__ void build_lists_kernel(const float* __restrict__ r) {
    int u = blockIdx.x, t = threadIdx.x;
    __shared__ int scnt;
    if (t == 0) scnt = 0;
    __syncthreads();
    for (int c = t; c < NI; c += 256) {
        if (r[(size_t)u * NI + c] > 0.0f) {
            int p = atomicAdd(&scnt, 1);
            if (p < MAXDEG) g_uitems[u * MAXDEG + p] = c;
            int q = atomicAdd(&g_icnt[c], 1);
            if (q < MAXDEG) g_iusers[c * MAXDEG + q] = u;
        }
    }
    __syncthreads();
    if (t == 0) g_ucnt[u] = scnt;
}

__global__ void invdeg_kernel() {
    int j = blockIdx.x * 256 + threadIdx.x;
    if (j < NN) {
        int c = (j < NU) ? g_ucnt[j] : g_icnt[j - NU];
        g_invdeg[j] = 1.0f / (float)(c + 1);
    }
}

// ---------- zero piA ----------
__global__ void zero_piA_kernel() {
    size_t i = (size_t)blockIdx.x * 256 + threadIdx.x;
    float4 z = make_float4(0.f, 0.f, 0.f, 0.f);
    float4* p = (float4*)g_piA;
    size_t total = (size_t)NN * NU / 4;
    for (size_t k = i; k < total; k += (size_t)gridDim.x * 256) p[k] = z;
}

// ---------- build pi2 (after 2 PPR steps) analytically, sparse scatter ----------
// pi2T[m][u] = 0.85 * sum_j pi1[u][j] * P[j][m] + 0.15*[m==u]
// pi1[u][u] = 0.85*duinv(u) + 0.15 ; pi1[u][item j in N(u)] = 0.85*duinv(u)
__global__ void pi2_build_kernel() {
    int u = blockIdx.x, t = threadIdx.x;
    int lane = t & 31, wid = t >> 5;
    __shared__ int items[MAXDEG];
    __shared__ int du_s;
    if (t == 0) du_s = min(g_ucnt[u], MAXDEG);
    __syncthreads();
    int d = du_s;
    for (int l = t; l < d; l += 256) items[l] = g_uitems[u * MAXDEG + l];
    __syncthreads();
    float duv = g_invdeg[u];
    float v0 = 0.85f * duv + 0.15f;   // pi1[u][u]
    float vI = 0.85f * duv;           // pi1[u][item]
    if (t == 0) {
        // j=u contributes to m=u via P[u][u]=duv, plus restart term
        atomicAdd(&g_piA[(size_t)u * NU + u], 0.85f * v0 * duv + 0.15f);
    }
    // j=u contributes to items m in N(u) via P[u][m]=duv
    for (int l = t; l < d; l += 256) {
        int m = NU + items[l];
        atomicAdd(&g_piA[(size_t)m * NU + u], 0.85f * v0 * duv);
    }
    // j = item in N(u): contributes to m=j and m in users(j), weight 0.85*vI*invdeg(j)
    for (int l = wid; l < d; l += 8) {
        int it = items[l];
        float div = g_invdeg[NU + it];
        float add = 0.85f * vI * div;
        if (lane == 0) atomicAdd(&g_piA[(size_t)(NU + it) * NU + u], add);
        int cj = min(g_icnt[it], MAXDEG);
        for (int q = lane; q < cj; q += 32) {
            int up = g_iusers[it * MAXDEG + q];
            atomicAdd(&g_piA[(size_t)up * NU + u], add);
        }
    }
}

// ---------- one dense PPR step: pout[j,:] = 0.85*(P^T pin)[j,:] + restart ----------
__global__ void __launch_bounds__(256) ppr_step_kernel(int flip, int jbase) {
    const float* __restrict__ pin = flip ? g_piB : g_piA;
    float* __restrict__ pout      = flip ? g_piA : g_piB;
    int j = jbase + blockIdx.x;
    int t = threadIdx.x;
    __shared__ int   nbr[MAXDEG];
    __shared__ float nw[MAXDEG];
    __shared__ int   Ls;
    if (t == 0) Ls = min((j < NU) ? g_ucnt[j] : g_icnt[j - NU], MAXDEG);
    __syncthreads();
    int L = Ls;
    if (j < NU) { for (int l = t; l < L; l += 256) nbr[l] = NU + g_uitems[j * MAXDEG + l]; }
    else        { for (int l = t; l < L; l += 256) nbr[l] = g_iusers[(j - NU) * MAXDEG + l]; }
    __syncthreads();
    for (int l = t; l < L; l += 256) nw[l] = g_invdeg[nbr[l]];
    __syncthreads();

    int u0 = t * 16;
    float dj = g_invdeg[j];
    float acc[16];
    {
        const float4* p = (const float4*)(pin + (size_t)j * NU + u0);
        float4 p0 = p[0], p1 = p[1], p2 = p[2], p3 = p[3];
        acc[0]=p0.x*dj; acc[1]=p0.y*dj; acc[2]=p0.z*dj; acc[3]=p0.w*dj;
        acc[4]=p1.x*dj; acc[5]=p1.y*dj; acc[6]=p1.z*dj; acc[7]=p1.w*dj;
        acc[8]=p2.x*dj; acc[9]=p2.y*dj; acc[10]=p2.z*dj; acc[11]=p2.w*dj;
        acc[12]=p3.x*dj; acc[13]=p3.y*dj; acc[14]=p3.z*dj; acc[15]=p3.w*dj;
    }
    for (int l = 0; l < L; ++l) {
        const float4* q = (const float4*)(pin + (size_t)nbr[l] * NU + u0);
        float4 q0 = q[0], q1 = q[1], q2 = q[2], q3 = q[3];
        float w = nw[l];
        acc[0]=fmaf(q0.x,w,acc[0]);  acc[1]=fmaf(q0.y,w,acc[1]);
        acc[2]=fmaf(q0.z,w,acc[2]);  acc[3]=fmaf(q0.w,w,acc[3]);
        acc[4]=fmaf(q1.x,w,acc[4]);  acc[5]=fmaf(q1.y,w,acc[5]);
        acc[6]=fmaf(q1.z,w,acc[6]);  acc[7]=fmaf(q1.w,w,acc[7]);
        acc[8]=fmaf(q2.x,w,acc[8]);  acc[9]=fmaf(q2.y,w,acc[9]);
        acc[10]=fmaf(q2.z,w,acc[10]); acc[11]=fmaf(q2.w,w,acc[11]);
        acc[12]=fmaf(q3.x,w,acc[12]); acc[13]=fmaf(q3.y,w,acc[13]);
        acc[14]=fmaf(q3.z,w,acc[14]); acc[15]=fmaf(q3.w,w,acc[15]);
    }
    #pragma unroll
    for (int i = 0; i < 16; ++i) acc[i] *= ONEM;
    int du = j - u0;
    if (du >= 0 && du < 16 && j < NU) acc[du] += DELTA;
    float4* o = (float4*)(pout + (size_t)j * NU + u0);
    o[0] = make_float4(acc[0], acc[1], acc[2], acc[3]);
    o[1] = make_float4(acc[4], acc[5], acc[6], acc[7]);
    o[2] = make_float4(acc[8], acc[9], acc[10], acc[11]);
    o[3] = make_float4(acc[12], acc[13], acc[14], acc[15]);
}

// ---------- masked scores, transposed into g_sim[u][it] ----------
__global__ void scores_kernel(const float* __restrict__ r) {
    __shared__ float tile[32][33];
    int it0 = blockIdx.x * 32, u0 = blockIdx.y * 32;
    int tx = threadIdx.x, ty = threadIdx.y;
    tile[ty][tx] = g_piB[(size_t)(NU + it0 + ty) * NU + u0 + tx];
    __syncthreads();
    int u = u0 + ty, it = it0 + tx;
    float sc = tile[tx][ty];
    float rv = r[(size_t)u * NI + it];
    g_sim[(size_t)u * NI + it] = (rv > 0.0f) ? -INFINITY : sc;
}

// ---------- copy r_train into UI and IU blocks ----------
__global__ void copy_r_kernel(const float* __restrict__ r, float* __restrict__ adj) {
    __shared__ float tile[32][33];
    int it0 = blockIdx.x * 32, u0 = blockIdx.y * 32;
    int tx = threadIdx.x, ty = threadIdx.y;
    float v = r[(size_t)(u0 + ty) * NI + it0 + tx];
    adj[(size_t)(u0 + ty) * NN + NU + it0 + tx] = v;
    tile[ty][tx] = v;
    __syncthreads();
    adj[(size_t)(NU + it0 + ty) * NN + u0 + tx] = tile[tx][ty];
}

// ---------- PPR top-K extra edges (register-resident) ----------
__global__ void __launch_bounds__(256) ppr_topk_kernel(float* __restrict__ adj) {
    int u = blockIdx.x, t = threadIdx.x;
    float v[16];
    const float* srow = g_sim + (size_t)u * NI;
    #pragma unroll
    for (int p = 0; p < 16; ++p) v[p] = srow[t + p * 256];
    __shared__ float swv[8];
    __shared__ int   swi[8];
    __shared__ float selv[PPRK];
    __shared__ int   seli[PPRK];
    __shared__ int   bsel;
    for (int k = 0; k < PPRK; ++k) {
        float bv = v[0]; int bp = 0;
        #pragma unroll
        for (int p = 1; p < 16; ++p) if (v[p] > bv) { bv = v[p]; bp = p; }
        int bc = t + bp * 256;
        #pragma unroll
        for (int o = 16; o; o >>= 1) {
            float ov = __shfl_xor_sync(0xffffffff, bv, o);
            int   oc = __shfl_xor_sync(0xffffffff, bc, o);
            if (ov > bv || (ov == bv && oc < bc)) { bv = ov; bc = oc; }
        }
        if ((t & 31) == 0) { swv[t >> 5] = bv; swi[t >> 5] = bc; }
        __syncthreads();
        if (t == 0) {
            float BV = swv[0]; int BC = swi[0];
            #pragma unroll
            for (int w = 1; w < 8; ++w)
                if (swv[w] > BV || (swv[w] == BV && swi[w] < BC)) { BV = swv[w]; BC = swi[w]; }
            selv[k] = BV; seli[k] = BC; bsel = BC;
        }
        __syncthreads();
        int sc = bsel;
        if ((sc & 255) == t) v[sc >> 8] = -INFINITY;
    }
    if (t < PPRK) {
        float w  = fmaxf(selv[t], 0.0f);
        float mx = fmaxf(selv[0], 0.0f);
        if (mx > 0.0f) w = w / fmaxf(mx, 1e-12f);
        int it = seli[t];
        adj[(size_t)u * NN + NU + it] = w;
        adj[(size_t)(NU + it) * NN + u] = w;
    }
}

// ---------- symmetric normalization ----------
__global__ void rowsum_kernel(const float* __restrict__ adj) {
    int i = blockIdx.x, t = threadIdx.x;
    const float4* row = (const float4*)(adj + (size_t)i * NN);
    float s = 0.0f;
    #pragma unroll
    for (int c = t; c < NN / 4; c += 256) {
        float4 x = row[c];
        s += (x.x + x.y) + (x.z + x.w);
    }
    __shared__ float sm[256];
    sm[t] = s;
    __syncthreads();
    for (int o = 128; o; o >>= 1) {
        if (t < o) sm[t] += sm[t + o];
        __syncthreads();
    }
    if (t == 0) {
        float rs = sm[0];
        g_dinv[i] = (rs > 0.0f) ? rsqrtf(fmaxf(rs, 1e-12f)) : 0.0f;
    }
}

__global__ void scale_kernel(float* __restrict__ adj) {
    size_t idx = ((size_t)blockIdx.x * 256 + threadIdx.x) * 4;
    size_t i = idx >> 13;           // / NN
    size_t j = idx & (NN - 1);
    float di = g_dinv[i];
    float4 v = *(float4*)&adj[idx];
    v.x *= di * g_dinv[j + 0];
    v.y *= di * g_dinv[j + 1];
    v.z *= di * g_dinv[j + 2];
    v.w *= di * g_dinv[j + 3];
    *(float4*)&adj[idx] = v;
}

// ---------- launch ----------
extern "C" void kernel_launch(void* const* d_in, const int* in_sizes, int n_in,
                              void* d_out, int out_size) {
    const float* fu = (const float*)d_in[0];
    const float* fi = (const float*)d_in[1];
    const float* r  = (const float*)d_in[2];
    float* out = (float*)d_out;

    zero_quad_kernel<<<NN, 256>>>(out);
    normalize_kernel<<<NN, 128>>>(fu, fi);

    dim3 gs(32, 32);
    syrk_kernel<<<gs, 256>>>(0);
    knn_topk_kernel<<<NU, 256>>>(out, 0);
    syrk_kernel<<<gs, 256>>>(NU);
    knn_topk_kernel<<<NI, 256>>>(out, NU);

    zero_counts_kernel<<<16, 256>>>();
    build_lists_kernel<<<NU, 256>>>(r);
    invdeg_kernel<<<32, 256>>>();

    zero_piA_kernel<<<2048, 256>>>();
    pi2_build_kernel<<<NU, 256>>>();

    ppr_step_kernel<<<NN, 256>>>(0, 0);    // step 3: A -> B (all rows)
    ppr_step_kernel<<<NN, 256>>>(1, 0);    // step 4: B -> A (all rows)
    ppr_step_kernel<<<NI, 256>>>(0, NU);   // step 5: A -> B (item rows only)

    dim3 t32(32, 32);
    dim3 g128(NI / 32, NU / 32);
    scores_kernel<<<g128, t32>>>(r);
    copy_r_kernel<<<g128, t32>>>(r, out);
    ppr_topk_kernel<<<NU, 256>>>(out);

    rowsum_kernel<<<NN, 256>>>(out);
    scale_kernel<<<(int)(((size_t)NN * NN) / 1024), 256>>>(out);
}

// round 5
// speedup vs baseline: 1.1169x; 1.0415x over previous
#include <cuda_runtime.h>
#include <math.h>

#define NU 4096
#define NI 4096
#define NN 8192
#define D  128
#define KNN 10
#define PPRK 20
#define MAXDEG 256
#define KCAP 128
#define ICAP 512
#define DELTA 0.15f
#define ONEM  0.85f

// ---------- static device scratch ----------
__device__ float g_xn[(size_t)NN * D];
__device__ float g_sim[(size_t)NU * NI];
__device__ float g_piA[(size_t)NN * NU];
__device__ float g_piB[(size_t)NN * NU];
__device__ int   g_uitems[NU * MAXDEG];
__device__ int   g_iusers[NI * MAXDEG];
__device__ int   g_ucnt[NU];
__device__ int   g_icnt[NI];
__device__ float g_invdeg[NN];
__device__ float g_dinv[NN];
// knn edge lists (global node ids in col)
__device__ int   g_knn_cnt[NN];
__device__ int   g_knn_col[(size_t)NN * KCAP];
__device__ float g_knn_w[(size_t)NN * KCAP];
__device__ float g_knnsum[NN];
// ppr extra edges
__device__ int   g_extra_it[NU * PPRK];
__device__ float g_extra_w[NU * PPRK];
__device__ int   g_extra_icnt[NI];
__device__ int   g_extra_iu[(size_t)NI * ICAP];
__device__ float g_extra_iw[(size_t)NI * ICAP];
__device__ float g_extra_isum[NI];
// r sums
__device__ float g_rrow[NU];
__device__ float g_rcol[NI];

// ---------- zero all counters ----------
__global__ void zero_counts_kernel() {
    int i = blockIdx.x * 256 + threadIdx.x;   // 0..8191
    g_knn_cnt[i] = 0;
    if (i < NU) g_ucnt[i] = 0;
    if (i < NI) {
        g_icnt[i] = 0;
        g_extra_icnt[i] = 0;
        g_extra_isum[i] = 0.0f;
        g_rcol[i] = 0.0f;
    }
}

// ---------- row-normalize features ----------
__global__ void normalize_kernel(const float* __restrict__ fu, const float* __restrict__ fi) {
    int row = blockIdx.x;
    int t = threadIdx.x; // 128 threads
    const float* src = (row < NU) ? &fu[(size_t)row * D] : &fi[(size_t)(row - NU) * D];
    float v = src[t];
    float s = v * v;
    #pragma unroll
    for (int o = 16; o; o >>= 1) s += __shfl_xor_sync(0xffffffff, s, o);
    __shared__ float ws[4];
    if ((t & 31) == 0) ws[t >> 5] = s;
    __syncthreads();
    float tot = ws[0] + ws[1] + ws[2] + ws[3];
    g_xn[(size_t)row * D + t] = v / fmaxf(sqrtf(tot), 1e-12f);
}

// ---------- r row sums (one warp per user row) ----------
__global__ void rsum_user_kernel(const float* __restrict__ r) {
    int row = blockIdx.x * 8 + (threadIdx.x >> 5);
    int lane = threadIdx.x & 31;
    const float4* p = (const float4*)(r + (size_t)row * NI);
    float s = 0.0f;
    for (int c = lane; c < NI / 4; c += 32) {
        float4 x = p[c];
        s += (x.x + x.y) + (x.z + x.w);
    }
    #pragma unroll
    for (int o = 16; o; o >>= 1) s += __shfl_xor_sync(0xffffffff, s, o);
    if (lane == 0) g_rrow[row] = s;
}

// ---------- r col sums (tiles, atomicAdd) ----------
__global__ void rsum_col_kernel(const float* __restrict__ r) {
    int i0 = blockIdx.x * 32, u0 = blockIdx.y * 256;
    int tx = threadIdx.x, ty = threadIdx.y;   // (32,8)
    float s = 0.0f;
    for (int k = 0; k < 32; ++k) {
        int u = u0 + ty * 32 + k;
        s += r[(size_t)u * NI + i0 + tx];
    }
    __shared__ float sm[8][32];
    sm[ty][tx] = s;
    __syncthreads();
    if (ty == 0) {
        float tot = 0.0f;
        #pragma unroll
        for (int q = 0; q < 8; ++q) tot += sm[q][tx];
        atomicAdd(&g_rcol[i0 + tx], tot);
    }
}

// ---------- SYRK: sim = Xn Xn^T ----------
__global__ void __launch_bounds__(256) syrk_kernel(int base) {
    int bm = blockIdx.y * 128, bn = blockIdx.x * 128;
    if (bn < bm) return;
    __shared__ float As[16][132];
    __shared__ float Bs[16][132];
    int tid = threadIdx.x;
    int tx = tid & 15, ty = tid >> 4;
    const float* X = g_xn + (size_t)base * D;
    float acc[8][8] = {};
    for (int k0 = 0; k0 < D; k0 += 16) {
        #pragma unroll
        for (int l = 0; l < 2; ++l) {
            int idx = tid * 2 + l;
            int rr  = idx >> 2;
            int c4  = (idx & 3) * 4;
            float4 a = *(const float4*)&X[(size_t)(bm + rr) * D + k0 + c4];
            As[c4 + 0][rr] = a.x; As[c4 + 1][rr] = a.y;
            As[c4 + 2][rr] = a.z; As[c4 + 3][rr] = a.w;
            float4 b = *(const float4*)&X[(size_t)(bn + rr) * D + k0 + c4];
            Bs[c4 + 0][rr] = b.x; Bs[c4 + 1][rr] = b.y;
            Bs[c4 + 2][rr] = b.z; Bs[c4 + 3][rr] = b.w;
        }
        __syncthreads();
        #pragma unroll
        for (int k = 0; k < 16; ++k) {
            float a[8], b[8];
            *(float4*)&a[0] = *(const float4*)&As[k][ty * 8];
            *(float4*)&a[4] = *(const float4*)&As[k][ty * 8 + 4];
            *(float4*)&b[0] = *(const float4*)&Bs[k][tx * 8];
            *(float4*)&b[4] = *(const float4*)&Bs[k][tx * 8 + 4];
            #pragma unroll
            for (int i = 0; i < 8; ++i)
                #pragma unroll
                for (int j = 0; j < 8; ++j) acc[i][j] = fmaf(a[i], b[j], acc[i][j]);
        }
        __syncthreads();
    }
    #pragma unroll
    for (int i = 0; i < 8; ++i) {
        size_t ro = (size_t)(bm + ty * 8 + i) * NI + bn + tx * 8;
        *(float4*)&g_sim[ro]     = make_float4(acc[i][0], acc[i][1], acc[i][2], acc[i][3]);
        *(float4*)&g_sim[ro + 4] = make_float4(acc[i][4], acc[i][5], acc[i][6], acc[i][7]);
    }
    if (bm != bn) {
        #pragma unroll
        for (int j = 0; j < 8; ++j) {
            size_t ro = (size_t)(bn + tx * 8 + j) * NI + bm + ty * 8;
            *(float4*)&g_sim[ro]     = make_float4(acc[0][j], acc[1][j], acc[2][j], acc[3][j]);
            *(float4*)&g_sim[ro + 4] = make_float4(acc[4][j], acc[5][j], acc[6][j], acc[7][j]);
        }
    }
}

// ---------- KNN top-K with cached per-thread argmax; edges to lists ----------
__global__ void __launch_bounds__(256) knn_topk_kernel(int base) {
    int row = blockIdx.x, t = threadIdx.x;
    float v[16];
    const float* srow = g_sim + (size_t)row * NI;
    #pragma unroll
    for (int p = 0; p < 16; ++p) {
        int c = t + p * 256;
        float x = srow[c];
        v[p] = (c == row) ? -INFINITY : x;
    }
    float bv = v[0]; int bp = 0;
    #pragma unroll
    for (int p = 1; p < 16; ++p) if (v[p] > bv) { bv = v[p]; bp = p; }

    __shared__ float swv[8];
    __shared__ int   swi[8];
    __shared__ int   bsel;
    for (int k = 0; k < KNN; ++k) {
        float wv = bv; int wc = t + bp * 256;
        #pragma unroll
        for (int o = 16; o; o >>= 1) {
            float ov = __shfl_xor_sync(0xffffffff, wv, o);
            int   oc = __shfl_xor_sync(0xffffffff, wc, o);
            if (ov > wv || (ov == wv && oc < wc)) { wv = ov; wc = oc; }
        }
        if ((t & 31) == 0) { swv[t >> 5] = wv; swi[t >> 5] = wc; }
        __syncthreads();
        if (t == 0) {
            float BV = swv[0]; int BC = swi[0];
            #pragma unroll
            for (int w = 1; w < 8; ++w)
                if (swv[w] > BV || (swv[w] == BV && swi[w] < BC)) { BV = swv[w]; BC = swi[w]; }
            bsel = BC;
            float wgt = fminf(fmaxf((BV + 1.0f) * 0.5f, 1e-6f), 1.0f);
            int gi = base + row, gj = base + BC;
            int a = atomicAdd(&g_knn_cnt[gi], 1);
            if (a < KCAP) { g_knn_col[(size_t)gi * KCAP + a] = gj; g_knn_w[(size_t)gi * KCAP + a] = wgt; }
            int b = atomicAdd(&g_knn_cnt[gj], 1);
            if (b < KCAP) { g_knn_col[(size_t)gj * KCAP + b] = gi; g_knn_w[(size_t)gj * KCAP + b] = wgt; }
        }
        __syncthreads();
        int sc = bsel;
        if ((sc & 255) == t) {
            v[sc >> 8] = -INFINITY;
            bv = v[0]; bp = 0;
            #pragma unroll
            for (int p = 1; p < 16; ++p) if (v[p] > bv) { bv = v[p]; bp = p; }
        }
    }
}

// ---------- bipartite adjacency lists ----------
__global__ void build_lists_kernel(const float* __restrict__ r) {
    int u = blockIdx.x, t = threadIdx.x;
    __shared__ int scnt;
    if (t == 0) scnt = 0;
    __syncthreads();
    for (int c = t; c < NI; c += 256) {
        if (r[(size_t)u * NI + c] > 0.0f) {
            int p = atomicAdd(&scnt, 1);
            if (p < MAXDEG) g_uitems[u * MAXDEG + p] = c;
            int q = atomicAdd(&g_icnt[c], 1);
            if (q < MAXDEG) g_iusers[c * MAXDEG + q] = u;
        }
    }
    __syncthreads();
    if (t == 0) g_ucnt[u] = scnt;
}

__global__ void invdeg_kernel() {
    int j = blockIdx.x * 256 + threadIdx.x;
    if (j < NN) {
        int c = (j < NU) ? g_ucnt[j] : g_icnt[j - NU];
        g_invdeg[j] = 1.0f / (float)(c + 1);
    }
}

__global__ void zero_piA_kernel() {
    size_t i = (size_t)blockIdx.x * 256 + threadIdx.x;
    float4 z = make_float4(0.f, 0.f, 0.f, 0.f);
    float4* p = (float4*)g_piA;
    size_t total = (size_t)NN * NU / 4;
    for (size_t k = i; k < total; k += (size_t)gridDim.x * 256) p[k] = z;
}

// ---------- build pi2 analytically ----------
__global__ void pi2_build_kernel() {
    int u = blockIdx.x, t = threadIdx.x;
    int lane = t & 31, wid = t >> 5;
    __shared__ int items[MAXDEG];
    __shared__ int du_s;
    if (t == 0) du_s = min(g_ucnt[u], MAXDEG);
    __syncthreads();
    int d = du_s;
    for (int l = t; l < d; l += 256) items[l] = g_uitems[u * MAXDEG + l];
    __syncthreads();
    float duv = g_invdeg[u];
    float v0 = 0.85f * duv + 0.15f;
    float vI = 0.85f * duv;
    if (t == 0) atomicAdd(&g_piA[(size_t)u * NU + u], 0.85f * v0 * duv + 0.15f);
    for (int l = t; l < d; l += 256) {
        int m = NU + items[l];
        atomicAdd(&g_piA[(size_t)m * NU + u], 0.85f * v0 * duv);
    }
    for (int l = wid; l < d; l += 8) {
        int it = items[l];
        float div = g_invdeg[NU + it];
        float add = 0.85f * vI * div;
        if (lane == 0) atomicAdd(&g_piA[(size_t)(NU + it) * NU + u], add);
        int cj = min(g_icnt[it], MAXDEG);
        for (int q = lane; q < cj; q += 32) {
            int up = g_iusers[it * MAXDEG + q];
            atomicAdd(&g_piA[(size_t)up * NU + u], add);
        }
    }
}

// ---------- dense PPR step ----------
__global__ void __launch_bounds__(256) ppr_step_kernel(int flip, int jbase) {
    const float* __restrict__ pin = flip ? g_piB : g_piA;
    float* __restrict__ pout      = flip ? g_piA : g_piB;
    int j = jbase + blockIdx.x;
    int t = threadIdx.x;
    __shared__ int   nbr[MAXDEG];
    __shared__ float nw[MAXDEG];
    __shared__ int   Ls;
    if (t == 0) Ls = min((j < NU) ? g_ucnt[j] : g_icnt[j - NU], MAXDEG);
    __syncthreads();
    int L = Ls;
    if (j < NU) { for (int l = t; l < L; l += 256) nbr[l] = NU + g_uitems[j * MAXDEG + l]; }
    else        { for (int l = t; l < L; l += 256) nbr[l] = g_iusers[(j - NU) * MAXDEG + l]; }
    __syncthreads();
    for (int l = t; l < L; l += 256) nw[l] = g_invdeg[nbr[l]];
    __syncthreads();

    int u0 = t * 16;
    float dj = g_invdeg[j];
    float acc[16];
    {
        const float4* p = (const float4*)(pin + (size_t)j * NU + u0);
        float4 p0 = p[0], p1 = p[1], p2 = p[2], p3 = p[3];
        acc[0]=p0.x*dj; acc[1]=p0.y*dj; acc[2]=p0.z*dj; acc[3]=p0.w*dj;
        acc[4]=p1.x*dj; acc[5]=p1.y*dj; acc[6]=p1.z*dj; acc[7]=p1.w*dj;
        acc[8]=p2.x*dj; acc[9]=p2.y*dj; acc[10]=p2.z*dj; acc[11]=p2.w*dj;
        acc[12]=p3.x*dj; acc[13]=p3.y*dj; acc[14]=p3.z*dj; acc[15]=p3.w*dj;
    }
    for (int l = 0; l < L; ++l) {
        const float4* q = (const float4*)(pin + (size_t)nbr[l] * NU + u0);
        float4 q0 = q[0], q1 = q[1], q2 = q[2], q3 = q[3];
        float w = nw[l];
        acc[0]=fmaf(q0.x,w,acc[0]);   acc[1]=fmaf(q0.y,w,acc[1]);
        acc[2]=fmaf(q0.z,w,acc[2]);   acc[3]=fmaf(q0.w,w,acc[3]);
        acc[4]=fmaf(q1.x,w,acc[4]);   acc[5]=fmaf(q1.y,w,acc[5]);
        acc[6]=fmaf(q1.z,w,acc[6]);   acc[7]=fmaf(q1.w,w,acc[7]);
        acc[8]=fmaf(q2.x,w,acc[8]);   acc[9]=fmaf(q2.y,w,acc[9]);
        acc[10]=fmaf(q2.z,w,acc[10]); acc[11]=fmaf(q2.w,w,acc[11]);
        acc[12]=fmaf(q3.x,w,acc[12]); acc[13]=fmaf(q3.y,w,acc[13]);
        acc[14]=fmaf(q3.z,w,acc[14]); acc[15]=fmaf(q3.w,w,acc[15]);
    }
    #pragma unroll
    for (int i = 0; i < 16; ++i) acc[i] *= ONEM;
    int du = j - u0;
    if (du >= 0 && du < 16 && j < NU) acc[du] += DELTA;
    float4* o = (float4*)(pout + (size_t)j * NU + u0);
    o[0] = make_float4(acc[0], acc[1], acc[2], acc[3]);
    o[1] = make_float4(acc[4], acc[5], acc[6], acc[7]);
    o[2] = make_float4(acc[8], acc[9], acc[10], acc[11]);
    o[3] = make_float4(acc[12], acc[13], acc[14], acc[15]);
}

// ---------- masked scores, transposed into g_sim[u][it] ----------
__global__ void scores_kernel(const float* __restrict__ r) {
    __shared__ float tile[32][33];
    int it0 = blockIdx.x * 32, u0 = blockIdx.y * 32;
    int tx = threadIdx.x, ty = threadIdx.y;
    tile[ty][tx] = g_piB[(size_t)(NU + it0 + ty) * NU + u0 + tx];
    __syncthreads();
    int u = u0 + ty, it = it0 + tx;
    float sc = tile[tx][ty];
    float rv = r[(size_t)u * NI + it];
    g_sim[(size_t)u * NI + it] = (rv > 0.0f) ? -INFINITY : sc;
}

// ---------- PPR top-K -> extra edge lists ----------
__global__ void __launch_bounds__(256) ppr_topk_kernel() {
    int u = blockIdx.x, t = threadIdx.x;
    float v[16];
    const float* srow = g_sim + (size_t)u * NI;
    #pragma unroll
    for (int p = 0; p < 16; ++p) v[p] = srow[t + p * 256];
    float bv = v[0]; int bp = 0;
    #pragma unroll
    for (int p = 1; p < 16; ++p) if (v[p] > bv) { bv = v[p]; bp = p; }

    __shared__ float swv[8];
    __shared__ int   swi[8];
    __shared__ float selv[PPRK];
    __shared__ int   seli[PPRK];
    __shared__ int   bsel;
    for (int k = 0; k < PPRK; ++k) {
        float wv = bv; int wc = t + bp * 256;
        #pragma unroll
        for (int o = 16; o; o >>= 1) {
            float ov = __shfl_xor_sync(0xffffffff, wv, o);
            int   oc = __shfl_xor_sync(0xffffffff, wc, o);
            if (ov > wv || (ov == wv && oc < wc)) { wv = ov; wc = oc; }
        }
        if ((t & 31) == 0) { swv[t >> 5] = wv; swi[t >> 5] = wc; }
        __syncthreads();
        if (t == 0) {
            float BV = swv[0]; int BC = swi[0];
            #pragma unroll
            for (int w = 1; w < 8; ++w)
                if (swv[w] > BV || (swv[w] == BV && swi[w] < BC)) { BV = swv[w]; BC = swi[w]; }
            selv[k] = BV; seli[k] = BC; bsel = BC;
        }
        __syncthreads();
        int sc = bsel;
        if ((sc & 255) == t) {
            v[sc >> 8] = -INFINITY;
            bv = v[0]; bp = 0;
            #pragma unroll
            for (int p = 1; p < 16; ++p) if (v[p] > bv) { bv = v[p]; bp = p; }
        }
    }
    if (t < PPRK) {
        float w  = fmaxf(selv[t], 0.0f);
        float mx = fmaxf(selv[0], 0.0f);
        if (mx > 0.0f) w = w / fmaxf(mx, 1e-12f);
        int it = seli[t];
        g_extra_it[u * PPRK + t] = it;
        g_extra_w[u * PPRK + t]  = w;
        atomicAdd(&g_extra_isum[it], w);
        int a = atomicAdd(&g_extra_icnt[it], 1);
        if (a < ICAP) { g_extra_iu[(size_t)it * ICAP + a] = u; g_extra_iw[(size_t)it * ICAP + a] = w; }
    }
}

// ---------- dedup'd KNN list sums (one warp per node) ----------
__global__ void knn_sum_kernel() {
    int node = blockIdx.x * 8 + (threadIdx.x >> 5);
    int lane = threadIdx.x & 31;
    int c = min(g_knn_cnt[node], KCAP);
    const int*   col = g_knn_col + (size_t)node * KCAP;
    const float* w   = g_knn_w   + (size_t)node * KCAP;
    float s = 0.0f;
    for (int e = lane; e < c; e += 32) {
        int cc = col[e];
        bool dup = false;
        for (int q = 0; q < e; ++q) if (col[q] == cc) { dup = true; break; }
        if (!dup) s += w[e];
    }
    #pragma unroll
    for (int o = 16; o; o >>= 1) s += __shfl_xor_sync(0xffffffff, s, o);
    if (lane == 0) g_knnsum[node] = s;
}

// ---------- total rowsum -> dinv ----------
__global__ void dinv_kernel() {
    int i = blockIdx.x * 256 + threadIdx.x;   // 0..8191
    float s = g_knnsum[i];
    if (i < NU) {
        s += g_rrow[i];
        #pragma unroll
        for (int k = 0; k < PPRK; ++k) s += g_extra_w[i * PPRK + k];
    } else {
        s += g_rcol[i - NU] + g_extra_isum[i - NU];
    }
    g_dinv[i] = (s > 0.0f) ? rsqrtf(fmaxf(s, 1e-12f)) : 0.0f;
}

// ---------- write user rows (full row, scaled) ----------
__global__ void __launch_bounds__(256) write_user_kernel(const float* __restrict__ r,
                                                         float* __restrict__ out) {
    int u = blockIdx.x, t = threadIdx.x;
    __shared__ float bufUU[NU];
    __shared__ float bufEx[NI];
    float4 z = make_float4(0.f, 0.f, 0.f, 0.f);
    #pragma unroll
    for (int q = t; q < NU / 4; q += 256) { ((float4*)bufUU)[q] = z; ((float4*)bufEx)[q] = z; }
    __syncthreads();
    int c = min(g_knn_cnt[u], KCAP);
    for (int l = t; l < c; l += 256) bufUU[g_knn_col[(size_t)u * KCAP + l]] = g_knn_w[(size_t)u * KCAP + l];
    if (t < PPRK) bufEx[g_extra_it[u * PPRK + t]] = g_extra_w[u * PPRK + t];
    __syncthreads();
    float du = g_dinv[u];
    size_t rowo = (size_t)u * NN;
    for (int q = t; q < NU / 4; q += 256) {
        float4 b  = ((float4*)bufUU)[q];
        float4 dv = *(const float4*)&g_dinv[q * 4];
        ((float4*)&out[rowo])[q] = make_float4(b.x * du * dv.x, b.y * du * dv.y,
                                               b.z * du * dv.z, b.w * du * dv.w);
    }
    const float4* rr = (const float4*)(r + (size_t)u * NI);
    for (int q = t; q < NI / 4; q += 256) {
        float4 rv = rr[q];
        float4 ex = ((float4*)bufEx)[q];
        float4 dv = *(const float4*)&g_dinv[NU + q * 4];
        ((float4*)&out[rowo + NU])[q] = make_float4((rv.x + ex.x) * du * dv.x,
                                                    (rv.y + ex.y) * du * dv.y,
                                                    (rv.z + ex.z) * du * dv.z,
                                                    (rv.w + ex.w) * du * dv.w);
    }
}

// ---------- write item rows II quadrant (scaled) ----------
__global__ void __launch_bounds__(256) write_item_kernel(float* __restrict__ out) {
    int i = blockIdx.x, t = threadIdx.x;
    int node = NU + i;
    __shared__ float buf[NI];
    float4 z = make_float4(0.f, 0.f, 0.f, 0.f);
    #pragma unroll
    for (int q = t; q < NI / 4; q += 256) ((float4*)buf)[q] = z;
    __syncthreads();
    int c = min(g_knn_cnt[node], KCAP);
    for (int l = t; l < c; l += 256)
        buf[g_knn_col[(size_t)node * KCAP + l] - NU] = g_knn_w[(size_t)node * KCAP + l];
    __syncthreads();
    float dn = g_dinv[node];
    size_t rowo = (size_t)node * NN + NU;
    for (int q = t; q < NI / 4; q += 256) {
        float4 b  = ((float4*)buf)[q];
        float4 dv = *(const float4*)&g_dinv[NU + q * 4];
        ((float4*)&out[rowo])[q] = make_float4(b.x * dn * dv.x, b.y * dn * dv.y,
                                               b.z * dn * dv.z, b.w * dn * dv.w);
    }
}

// ---------- IU quadrant: scaled transpose of r ----------
__global__ void write_IU_kernel(const float* __restrict__ r, float* __restrict__ out) {
    __shared__ float tile[32][33];
    int it0 = blockIdx.x * 32, u0 = blockIdx.y * 32;
    int tx = threadIdx.x, ty = threadIdx.y;
    tile[ty][tx] = r[(size_t)(u0 + ty) * NI + it0 + tx];
    __syncthreads();
    int i = it0 + ty, u = u0 + tx;
    out[(size_t)(NU + i) * NN + u] = tile[tx][ty] * g_dinv[NU + i] * g_dinv[u];
}

// ---------- scatter extra edges into IU quadrant ----------
__global__ void extra_IU_kernel(float* __restrict__ out) {
    int u = blockIdx.x, t = threadIdx.x;
    if (t < PPRK) {
        int it = g_extra_it[u * PPRK + t];
        float w = g_extra_w[u * PPRK + t];
        out[(size_t)(NU + it) * NN + u] = w * g_dinv[NU + it] * g_dinv[u];
    }
}

// ---------- launch ----------
extern "C" void kernel_launch(void* const* d_in, const int* in_sizes, int n_in,
                              void* d_out, int out_size) {
    const float* fu = (const float*)d_in[0];
    const float* fi = (const float*)d_in[1];
    const float* r  = (const float*)d_in[2];
    float* out = (float*)d_out;

    zero_counts_kernel<<<32, 256>>>();
    normalize_kernel<<<NN, 128>>>(fu, fi);
    rsum_user_kernel<<<NU / 8, 256>>>(r);
    rsum_col_kernel<<<dim3(NI / 32, NU / 256), dim3(32, 8)>>>(r);

    dim3 gs(32, 32);
    syrk_kernel<<<gs, 256>>>(0);
    knn_topk_kernel<<<NU, 256>>>(0);
    syrk_kernel<<<gs, 256>>>(NU);
    knn_topk_kernel<<<NI, 256>>>(NU);

    build_lists_kernel<<<NU, 256>>>(r);
    invdeg_kernel<<<32, 256>>>();

    zero_piA_kernel<<<2048, 256>>>();
    pi2_build_kernel<<<NU, 256>>>();

    ppr_step_kernel<<<NN, 256>>>(0, 0);    // pi2 -> pi3  (A->B)
    ppr_step_kernel<<<NN, 256>>>(1, 0);    // pi3 -> pi4  (B->A)
    ppr_step_kernel<<<NI, 256>>>(0, NU);   // pi4 -> pi5  (A->B, item rows)

    dim3 t32(32, 32);
    dim3 g128(NI / 32, NU / 32);
    scores_kernel<<<g128, t32>>>(r);
    ppr_topk_kernel<<<NU, 256>>>();

    knn_sum_kernel<<<NN / 8, 256>>>();
    dinv_kernel<<<32, 256>>>();

    write_user_kernel<<<NU, 256>>>(r, out);
    write_item_kernel<<<NI, 256>>>(out);
    write_IU_kernel<<<g128, t32>>>(r, out);
    extra_IU_kernel<<<NU, 32>>>(out);
}

// round 9
// speedup vs baseline: 1.7422x; 1.5598x over previous
#include <cuda_runtime.h>
#include <math.h>

#define NU 4096
#define NI 4096
#define NN 8192
#define D  128
#define KNN 10
#define PPRK 20
#define MAXDEG 256
#define KCAP 128
#define DELTA 0.15f
#define ONEM  0.85f

// ---------- static device scratch ----------
__device__ float g_xn[(size_t)NN * D];
__device__ float g_sim[(size_t)NU * NI];       // knn chain only
__device__ float g_scores[(size_t)NU * NI];    // ppr chain only
__device__ float g_piA[(size_t)NN * NU];
__device__ float g_piB[(size_t)NN * NU];
__device__ int   g_uitems[NU * MAXDEG];
__device__ int   g_iusers[NI * MAXDEG];
__device__ int   g_ucnt[NU];
__device__ int   g_icnt[NI];
__device__ float g_invdeg[NN];
__device__ float g_dinv[NN];
// knn edge lists (global node ids in col)
__device__ int   g_knn_cnt[NN];
__device__ int   g_knn_col[(size_t)NN * KCAP];
__device__ float g_knn_w[(size_t)NN * KCAP];
__device__ float g_knnsum[NN];
// ppr extra edges (user-side only; item-side is a scatter)
__device__ int   g_extra_it[NU * PPRK];
__device__ float g_extra_w[NU * PPRK];
__device__ float g_extra_isum[NI];

// ---------- zero all counters ----------
__global__ void zero_counts_kernel() {
    int i = blockIdx.x * 256 + threadIdx.x;   // 0..8191
    g_knn_cnt[i] = 0;
    if (i < NU) g_ucnt[i] = 0;
    if (i < NI) {
        g_icnt[i] = 0;
        g_extra_isum[i] = 0.0f;
    }
}

// ---------- row-normalize features ----------
__global__ void normalize_kernel(const float* __restrict__ fu, const float* __restrict__ fi) {
    int row = blockIdx.x;
    int t = threadIdx.x; // 128 threads
    const float* src = (row < NU) ? &fu[(size_t)row * D] : &fi[(size_t)(row - NU) * D];
    float v = src[t];
    float s = v * v;
    #pragma unroll
    for (int o = 16; o; o >>= 1) s += __shfl_xor_sync(0xffffffff, s, o);
    __shared__ float ws[4];
    if ((t & 31) == 0) ws[t >> 5] = s;
    __syncthreads();
    float tot = ws[0] + ws[1] + ws[2] + ws[3];
    g_xn[(size_t)row * D + t] = v / fmaxf(sqrtf(tot), 1e-12f);
}

// ---------- SYRK: sim = Xn Xn^T ----------
__global__ void __launch_bounds__(256) syrk_kernel(int base) {
    int bm = blockIdx.y * 128, bn = blockIdx.x * 128;
    if (bn < bm) return;
    __shared__ float As[16][132];
    __shared__ float Bs[16][132];
    int tid = threadIdx.x;
    int tx = tid & 15, ty = tid >> 4;
    const float* X = g_xn + (size_t)base * D;
    float acc[8][8] = {};
    for (int k0 = 0; k0 < D; k0 += 16) {
        #pragma unroll
        for (int l = 0; l < 2; ++l) {
            int idx = tid * 2 + l;
            int rr  = idx >> 2;
            int c4  = (idx & 3) * 4;
            float4 a = *(const float4*)&X[(size_t)(bm + rr) * D + k0 + c4];
            As[c4 + 0][rr] = a.x; As[c4 + 1][rr] = a.y;
            As[c4 + 2][rr] = a.z; As[c4 + 3][rr] = a.w;
            float4 b = *(const float4*)&X[(size_t)(bn + rr) * D + k0 + c4];
            Bs[c4 + 0][rr] = b.x; Bs[c4 + 1][rr] = b.y;
            Bs[c4 + 2][rr] = b.z; Bs[c4 + 3][rr] = b.w;
        }
        __syncthreads();
        #pragma unroll
        for (int k = 0; k < 16; ++k) {
            float a[8], b[8];
            *(float4*)&a[0] = *(const float4*)&As[k][ty * 8];
            *(float4*)&a[4] = *(const float4*)&As[k][ty * 8 + 4];
            *(float4*)&b[0] = *(const float4*)&Bs[k][tx * 8];
            *(float4*)&b[4] = *(const float4*)&Bs[k][tx * 8 + 4];
            #pragma unroll
            for (int i = 0; i < 8; ++i)
                #pragma unroll
                for (int j = 0; j < 8; ++j) acc[i][j] = fmaf(a[i], b[j], acc[i][j]);
        }
        __syncthreads();
    }
    #pragma unroll
    for (int i = 0; i < 8; ++i) {
        size_t ro = (size_t)(bm + ty * 8 + i) * NI + bn + tx * 8;
        *(float4*)&g_sim[ro]     = make_float4(acc[i][0], acc[i][1], acc[i][2], acc[i][3]);
        *(float4*)&g_sim[ro + 4] = make_float4(acc[i][4], acc[i][5], acc[i][6], acc[i][7]);
    }
    if (bm != bn) {
        #pragma unroll
        for (int j = 0; j < 8; ++j) {
            size_t ro = (size_t)(bn + tx * 8 + j) * NI + bm + ty * 8;
            *(float4*)&g_sim[ro]     = make_float4(acc[0][j], acc[1][j], acc[2][j], acc[3][j]);
            *(float4*)&g_sim[ro + 4] = make_float4(acc[4][j], acc[5][j], acc[6][j], acc[7][j]);
        }
    }
}

// ---------- KNN top-K with cached per-thread argmax; edges to lists ----------
__global__ void __launch_bounds__(256) knn_topk_kernel(int base) {
    int row = blockIdx.x, t = threadIdx.x;
    float v[16];
    const float* srow = g_sim + (size_t)row * NI;
    #pragma unroll
    for (int p = 0; p < 16; ++p) {
        int c = t + p * 256;
        float x = srow[c];
        v[p] = (c == row) ? -INFINITY : x;
    }
    float bv = v[0]; int bp = 0;
    #pragma unroll
    for (int p = 1; p < 16; ++p) if (v[p] > bv) { bv = v[p]; bp = p; }

    __shared__ float swv[8];
    __shared__ int   swi[8];
    __shared__ int   bsel;
    for (int k = 0; k < KNN; ++k) {
        float wv = bv; int wc = t + bp * 256;
        #pragma unroll
        for (int o = 16; o; o >>= 1) {
            float ov = __shfl_xor_sync(0xffffffff, wv, o);
            int   oc = __shfl_xor_sync(0xffffffff, wc, o);
            if (ov > wv || (ov == wv && oc < wc)) { wv = ov; wc = oc; }
        }
        if ((t & 31) == 0) { swv[t >> 5] = wv; swi[t >> 5] = wc; }
        __syncthreads();
        if (t == 0) {
            float BV = swv[0]; int BC = swi[0];
            #pragma unroll
            for (int w = 1; w < 8; ++w)
                if (swv[w] > BV || (swv[w] == BV && swi[w] < BC)) { BV = swv[w]; BC = swi[w]; }
            bsel = BC;
            float wgt = fminf(fmaxf((BV + 1.0f) * 0.5f, 1e-6f), 1.0f);
            int gi = base + row, gj = base + BC;
            int a = atomicAdd(&g_knn_cnt[gi], 1);
            if (a < KCAP) { g_knn_col[(size_t)gi * KCAP + a] = gj; g_knn_w[(size_t)gi * KCAP + a] = wgt; }
            int b = atomicAdd(&g_knn_cnt[gj], 1);
            if (b < KCAP) { g_knn_col[(size_t)gj * KCAP + b] = gi; g_knn_w[(size_t)gj * KCAP + b] = wgt; }
        }
        __syncthreads();
        int sc = bsel;
        if ((sc & 255) == t) {
            v[sc >> 8] = -INFINITY;
            bv = v[0]; bp = 0;
            #pragma unroll
            for (int p = 1; p < 16; ++p) if (v[p] > bv) { bv = v[p]; bp = p; }
        }
    }
}

// ---------- bipartite adjacency lists ----------
__global__ void build_lists_kernel(const float* __restrict__ r) {
    int u = blockIdx.x, t = threadIdx.x;
    __shared__ int scnt;
    if (t == 0) scnt = 0;
    __syncthreads();
    for (int c = t; c < NI; c += 256) {
        if (r[(size_t)u * NI + c] > 0.0f) {
            int p = atomicAdd(&scnt, 1);
            if (p < MAXDEG) g_uitems[u * MAXDEG + p] = c;
            int q = atomicAdd(&g_icnt[c], 1);
            if (q < MAXDEG) g_iusers[c * MAXDEG + q] = u;
        }
    }
    __syncthreads();
    if (t == 0) g_ucnt[u] = scnt;
}

__global__ void invdeg_kernel() {
    int j = blockIdx.x * 256 + threadIdx.x;
    if (j < NN) {
        int c = (j < NU) ? g_ucnt[j] : g_icnt[j - NU];
        g_invdeg[j] = 1.0f / (float)(c + 1);
    }
}

__global__ void zero_piA_kernel() {
    size_t i = (size_t)blockIdx.x * 256 + threadIdx.x;
    float4 z = make_float4(0.f, 0.f, 0.f, 0.f);
    float4* p = (float4*)g_piA;
    size_t total = (size_t)NN * NU / 4;
    for (size_t k = i; k < total; k += (size_t)gridDim.x * 256) p[k] = z;
}

// ---------- build pi2 analytically ----------
__global__ void pi2_build_kernel() {
    int u = blockIdx.x, t = threadIdx.x;
    int lane = t & 31, wid = t >> 5;
    __shared__ int items[MAXDEG];
    __shared__ int du_s;
    if (t == 0) du_s = min(g_ucnt[u], MAXDEG);
    __syncthreads();
    int d = du_s;
    for (int l = t; l < d; l += 256) items[l] = g_uitems[u * MAXDEG + l];
    __syncthreads();
    float duv = g_invdeg[u];
    float v0 = 0.85f * duv + 0.15f;
    float vI = 0.85f * duv;
    if (t == 0) atomicAdd(&g_piA[(size_t)u * NU + u], 0.85f * v0 * duv + 0.15f);
    for (int l = t; l < d; l += 256) {
        int m = NU + items[l];
        atomicAdd(&g_piA[(size_t)m * NU + u], 0.85f * v0 * duv);
    }
    for (int l = wid; l < d; l += 8) {
        int it = items[l];
        float div = g_invdeg[NU + it];
        float add = 0.85f * vI * div;
        if (lane == 0) atomicAdd(&g_piA[(size_t)(NU + it) * NU + u], add);
        int cj = min(g_icnt[it], MAXDEG);
        for (int q = lane; q < cj; q += 32) {
            int up = g_iusers[it * MAXDEG + q];
            atomicAdd(&g_piA[(size_t)up * NU + u], add);
        }
    }
}

// ---------- dense PPR step, u-chunked (1024 columns per launch) ----------
__global__ void __launch_bounds__(256) ppr_step_kernel(int flip, int jbase, int ubase) {
    const float* __restrict__ pin = flip ? g_piB : g_piA;
    float* __restrict__ pout      = flip ? g_piA : g_piB;
    int j = jbase + blockIdx.x;
    int t = threadIdx.x;
    __shared__ int   nbr[MAXDEG];
    __shared__ float nw[MAXDEG];
    __shared__ int   Ls;
    if (t == 0) Ls = min((j < NU) ? g_ucnt[j] : g_icnt[j - NU], MAXDEG);
    __syncthreads();
    int L = Ls;
    if (j < NU) { if (t < L) nbr[t] = NU + g_uitems[j * MAXDEG + t]; }
    else        { if (t < L) nbr[t] = g_iusers[(j - NU) * MAXDEG + t]; }
    __syncthreads();
    if (t < L) nw[t] = g_invdeg[nbr[t]];
    __syncthreads();

    int u0 = ubase + t * 4;
    float dj = g_invdeg[j];
    float4 p = *(const float4*)(pin + (size_t)j * NU + u0);
    float ax = p.x * dj, ay = p.y * dj, az = p.z * dj, aw = p.w * dj;
    for (int l = 0; l < L; ++l) {
        float4 q = *(const float4*)(pin + (size_t)nbr[l] * NU + u0);
        float w = nw[l];
        ax = fmaf(q.x, w, ax); ay = fmaf(q.y, w, ay);
        az = fmaf(q.z, w, az); aw = fmaf(q.w, w, aw);
    }
    ax *= ONEM; ay *= ONEM; az *= ONEM; aw *= ONEM;
    if (j < NU) {
        int du = j - u0;
        if (du == 0) ax += DELTA;
        else if (du == 1) ay += DELTA;
        else if (du == 2) az += DELTA;
        else if (du == 3) aw += DELTA;
    }
    *(float4*)(pout + (size_t)j * NU + u0) = make_float4(ax, ay, az, aw);
}

// ---------- transpose item-block of piB into g_scores[u][it] ----------
__global__ void transpose_scores_kernel() {
    __shared__ float tile[32][33];
    int it0 = blockIdx.x * 32, u0 = blockIdx.y * 32;
    int tx = threadIdx.x, ty = threadIdx.y;
    tile[ty][tx] = g_piB[(size_t)(NU + it0 + ty) * NU + u0 + tx];
    __syncthreads();
    g_scores[(size_t)(u0 + ty) * NI + it0 + tx] = tile[tx][ty];
}

// ---------- mask rated items with -inf (r is binary; positions = uitems) ----------
__global__ void mask_scores_kernel() {
    int u = blockIdx.x, lane = threadIdx.x;
    int d = min(g_ucnt[u], MAXDEG);
    for (int l = lane; l < d; l += 32)
        g_scores[(size_t)u * NI + g_uitems[u * MAXDEG + l]] = -INFINITY;
}

// ---------- PPR top-K -> user-side extra edge lists ----------
__global__ void __launch_bounds__(256) ppr_topk_kernel() {
    int u = blockIdx.x, t = threadIdx.x;
    float v[16];
    const float* srow = g_scores + (size_t)u * NI;
    #pragma unroll
    for (int p = 0; p < 16; ++p) v[p] = srow[t + p * 256];
    float bv = v[0]; int bp = 0;
    #pragma unroll
    for (int p = 1; p < 16; ++p) if (v[p] > bv) { bv = v[p]; bp = p; }

    __shared__ float swv[8];
    __shared__ int   swi[8];
    __shared__ float selv[PPRK];
    __shared__ int   seli[PPRK];
    __shared__ int   bsel;
    for (int k = 0; k < PPRK; ++k) {
        float wv = bv; int wc = t + bp * 256;
        #pragma unroll
        for (int o = 16; o; o >>= 1) {
            float ov = __shfl_xor_sync(0xffffffff, wv, o);
            int   oc = __shfl_xor_sync(0xffffffff, wc, o);
            if (ov > wv || (ov == wv && oc < wc)) { wv = ov; wc = oc; }
        }
        if ((t & 31) == 0) { swv[t >> 5] = wv; swi[t >> 5] = wc; }
        __syncthreads();
        if (t == 0) {
            float BV = swv[0]; int BC = swi[0];
            #pragma unroll
            for (int w = 1; w < 8; ++w)
                if (swv[w] > BV || (swv[w] == BV && swi[w] < BC)) { BV = swv[w]; BC = swi[w]; }
            selv[k] = BV; seli[k] = BC; bsel = BC;
        }
        __syncthreads();
        int sc = bsel;
        if ((sc & 255) == t) {
            v[sc >> 8] = -INFINITY;
            bv = v[0]; bp = 0;
            #pragma unroll
            for (int p = 1; p < 16; ++p) if (v[p] > bv) { bv = v[p]; bp = p; }
        }
    }
    if (t < PPRK) {
        float w  = fmaxf(selv[t], 0.0f);
        float mx = fmaxf(selv[0], 0.0f);
        if (mx > 0.0f) w = w / fmaxf(mx, 1e-12f);
        int it = seli[t];
        g_extra_it[u * PPRK + t] = it;
        g_extra_w[u * PPRK + t]  = w;
        atomicAdd(&g_extra_isum[it], w);
    }
}

// ---------- dedup'd KNN list sums (one warp per node) ----------
__global__ void knn_sum_kernel() {
    int node = blockIdx.x * 8 + (threadIdx.x >> 5);
    int lane = threadIdx.x & 31;
    int c = min(g_knn_cnt[node], KCAP);
    const int*   col = g_knn_col + (size_t)node * KCAP;
    const float* w   = g_knn_w   + (size_t)node * KCAP;
    float s = 0.0f;
    for (int e = lane; e < c; e += 32) {
        int cc = col[e];
        bool dup = false;
        for (int q = 0; q < e; ++q) if (col[q] == cc) { dup = true; break; }
        if (!dup) s += w[e];
    }
    #pragma unroll
    for (int o = 16; o; o >>= 1) s += __shfl_xor_sync(0xffffffff, s, o);
    if (lane == 0) g_knnsum[node] = s;
}

// ---------- total rowsum -> dinv (r sums = counts, since r is binary) ----------
__global__ void dinv_kernel() {
    int i = blockIdx.x * 256 + threadIdx.x;   // 0..8191
    float s = g_knnsum[i];
    if (i < NU) {
        s += (float)g_ucnt[i];
        #pragma unroll
        for (int k = 0; k < PPRK; ++k) s += g_extra_w[i * PPRK + k];
    } else {
        s += (float)g_icnt[i - NU] + g_extra_isum[i - NU];
    }
    g_dinv[i] = (s > 0.0f) ? rsqrtf(fmaxf(s, 1e-12f)) : 0.0f;
}

// ---------- write user rows (full row, scaled; no r read) ----------
__global__ void __launch_bounds__(256) write_user_kernel(float* __restrict__ out) {
    int u = blockIdx.x, t = threadIdx.x;
    __shared__ float bufUU[NU];
    __shared__ float bufUI[NI];
    float4 z = make_float4(0.f, 0.f, 0.f, 0.f);
    #pragma unroll
    for (int q = t; q < NU / 4; q += 256) { ((float4*)bufUU)[q] = z; ((float4*)bufUI)[q] = z; }
    __syncthreads();
    int c = min(g_knn_cnt[u], KCAP);
    for (int l = t; l < c; l += 256) bufUU[g_knn_col[(size_t)u * KCAP + l]] = g_knn_w[(size_t)u * KCAP + l];
    int d = min(g_ucnt[u], MAXDEG);
    for (int l = t; l < d; l += 256) bufUI[g_uitems[u * MAXDEG + l]] = 1.0f;
    if (t < PPRK) bufUI[g_extra_it[u * PPRK + t]] = g_extra_w[u * PPRK + t];
    __syncthreads();
    float du = g_dinv[u];
    size_t rowo = (size_t)u * NN;
    for (int q = t; q < NU / 4; q += 256) {
        float4 b  = ((float4*)bufUU)[q];
        float4 dv = *(const float4*)&g_dinv[q * 4];
        ((float4*)&out[rowo])[q] = make_float4(b.x * du * dv.x, b.y * du * dv.y,
                                               b.z * du * dv.z, b.w * du * dv.w);
    }
    for (int q = t; q < NI / 4; q += 256) {
        float4 b  = ((float4*)bufUI)[q];
        float4 dv = *(const float4*)&g_dinv[NU + q * 4];
        ((float4*)&out[rowo + NU])[q] = make_float4(b.x * du * dv.x, b.y * du * dv.y,
                                                    b.z * du * dv.z, b.w * du * dv.w);
    }
}

// ---------- write item rows (IU from rated users; extras patched after) ----------
__global__ void __launch_bounds__(256) write_item_kernel(float* __restrict__ out) {
    int i = blockIdx.x, t = threadIdx.x;
    int node = NU + i;
    __shared__ float bufIU[NU];
    __shared__ float bufII[NI];
    float4 z = make_float4(0.f, 0.f, 0.f, 0.f);
    #pragma unroll
    for (int q = t; q < NU / 4; q += 256) { ((float4*)bufIU)[q] = z; ((float4*)bufII)[q] = z; }
    __syncthreads();
    int c = min(g_knn_cnt[node], KCAP);
    for (int l = t; l < c; l += 256)
        bufII[g_knn_col[(size_t)node * KCAP + l] - NU] = g_knn_w[(size_t)node * KCAP + l];
    int d = min(g_icnt[i], MAXDEG);
    for (int l = t; l < d; l += 256) bufIU[g_iusers[i * MAXDEG + l]] = 1.0f;
    __syncthreads();
    float dn = g_dinv[node];
    size_t rowo = (size_t)node * NN;
    for (int q = t; q < NU / 4; q += 256) {
        float4 b  = ((float4*)bufIU)[q];
        float4 dv = *(const float4*)&g_dinv[q * 4];
        ((float4*)&out[rowo])[q] = make_float4(b.x * dn * dv.x, b.y * dn * dv.y,
                                               b.z * dn * dv.z, b.w * dn * dv.w);
    }
    for (int q = t; q < NI / 4; q += 256) {
        float4 b  = ((float4*)bufII)[q];
        float4 dv = *(const float4*)&g_dinv[NU + q * 4];
        ((float4*)&out[rowo + NU])[q] = make_float4(b.x * dn * dv.x, b.y * dn * dv.y,
                                                    b.z * dn * dv.z, b.w * dn * dv.w);
    }
}

// ---------- scatter extras into IU quadrant (user-side, uncapped) ----------
__global__ void extra_IU_kernel(float* __restrict__ out) {
    int u = blockIdx.x, t = threadIdx.x;
    if (t < PPRK) {
        int it = g_extra_it[u * PPRK + t];
        float w = g_extra_w[u * PPRK + t];
        out[(size_t)(NU + it) * NN + u] = w * g_dinv[NU + it] * g_dinv[u];
    }
}

// ---------- launch (single stream; capture-safe) ----------
extern "C" void kernel_launch(void* const* d_in, const int* in_sizes, int n_in,
                              void* d_out, int out_size) {
    const float* fu = (const float*)d_in[0];
    const float* fi = (const float*)d_in[1];
    const float* r  = (const float*)d_in[2];
    float* out = (float*)d_out;

    zero_counts_kernel<<<32, 256>>>();
    normalize_kernel<<<NN, 128>>>(fu, fi);

    dim3 gs(32, 32);
    syrk_kernel<<<gs, 256>>>(0);
    knn_topk_kernel<<<NU, 256>>>(0);
    syrk_kernel<<<gs, 256>>>(NU);
    knn_topk_kernel<<<NI, 256>>>(NU);
    knn_sum_kernel<<<NN / 8, 256>>>();

    build_lists_kernel<<<NU, 256>>>(r);
    invdeg_kernel<<<32, 256>>>();
    zero_piA_kernel<<<2048, 256>>>();
    pi2_build_kernel<<<NU, 256>>>();

    for (int c = 0; c < 4; ++c) ppr_step_kernel<<<NN, 256>>>(0, 0, c * 1024);   // pi2->pi3
    for (int c = 0; c < 4; ++c) ppr_step_kernel<<<NN, 256>>>(1, 0, c * 1024);   // pi3->pi4
    for (int c = 0; c < 4; ++c) ppr_step_kernel<<<NI, 256>>>(0, NU, c * 1024);  // pi4->pi5 (items)

    dim3 t32(32, 32);
    transpose_scores_kernel<<<dim3(NI / 32, NU / 32), t32>>>();
    mask_scores_kernel<<<NU, 32>>>();
    ppr_topk_kernel<<<NU, 256>>>();

    dinv_kernel<<<32, 256>>>();
    write_user_kernel<<<NU, 256>>>(out);
    write_item_kernel<<<NI, 256>>>(out);
    extra_IU_kernel<<<NU, 32>>>(out);
}

// round 10
// speedup vs baseline: 1.8392x; 1.0557x over previous
#include <cuda_runtime.h>
#include <math.h>

#define NU 4096
#define NI 4096
#define NN 8192
#define D  128
#define KNN 10
#define PPRK 20
#define MAXDEG 256
#define KCAP 128
#define DELTA 0.15f
#define ONEM  0.85f

// ---------- static device scratch ----------
__device__ float g_xn[(size_t)NN * D];
__device__ float g_sim[(size_t)NU * NI];       // knn chain only
__device__ float g_scores[(size_t)NU * NI];    // ppr chain only
__device__ float g_piA[(size_t)NN * NU];
__device__ float g_piB[(size_t)NN * NU];
__device__ int   g_uitems[NU * MAXDEG];
__device__ int   g_iusers[NI * MAXDEG];
__device__ int   g_ucnt[NU];
__device__ int   g_icnt[NI];
__device__ float g_invdeg[NN];
__device__ float g_dinv[NN];
// knn edge lists (global node ids in col)
__device__ int   g_knn_cnt[NN];
__device__ int   g_knn_col[(size_t)NN * KCAP];
__device__ float g_knn_w[(size_t)NN * KCAP];
__device__ float g_knnsum[NN];
// ppr extra edges (user-side only; item-side is a scatter)
__device__ int   g_extra_it[NU * PPRK];
__device__ float g_extra_w[NU * PPRK];
__device__ float g_extra_isum[NI];

// ---------- zero all counters ----------
__global__ void zero_counts_kernel() {
    int i = blockIdx.x * 256 + threadIdx.x;   // 0..8191
    g_knn_cnt[i] = 0;
    if (i < NU) g_ucnt[i] = 0;
    if (i < NI) {
        g_icnt[i] = 0;
        g_extra_isum[i] = 0.0f;
    }
}

// ---------- row-normalize features ----------
__global__ void normalize_kernel(const float* __restrict__ fu, const float* __restrict__ fi) {
    int row = blockIdx.x;
    int t = threadIdx.x; // 128 threads
    const float* src = (row < NU) ? &fu[(size_t)row * D] : &fi[(size_t)(row - NU) * D];
    float v = src[t];
    float s = v * v;
    #pragma unroll
    for (int o = 16; o; o >>= 1) s += __shfl_xor_sync(0xffffffff, s, o);
    __shared__ float ws[4];
    if ((t & 31) == 0) ws[t >> 5] = s;
    __syncthreads();
    float tot = ws[0] + ws[1] + ws[2] + ws[3];
    g_xn[(size_t)row * D + t] = v / fmaxf(sqrtf(tot), 1e-12f);
}

// ---------- SYRK: sim = Xn Xn^T ----------
__global__ void __launch_bounds__(256) syrk_kernel(int base) {
    int bm = blockIdx.y * 128, bn = blockIdx.x * 128;
    if (bn < bm) return;
    __shared__ float As[16][132];
    __shared__ float Bs[16][132];
    int tid = threadIdx.x;
    int tx = tid & 15, ty = tid >> 4;
    const float* X = g_xn + (size_t)base * D;
    float acc[8][8] = {};
    for (int k0 = 0; k0 < D; k0 += 16) {
        #pragma unroll
        for (int l = 0; l < 2; ++l) {
            int idx = tid * 2 + l;
            int rr  = idx >> 2;
            int c4  = (idx & 3) * 4;
            float4 a = *(const float4*)&X[(size_t)(bm + rr) * D + k0 + c4];
            As[c4 + 0][rr] = a.x; As[c4 + 1][rr] = a.y;
            As[c4 + 2][rr] = a.z; As[c4 + 3][rr] = a.w;
            float4 b = *(const float4*)&X[(size_t)(bn + rr) * D + k0 + c4];
            Bs[c4 + 0][rr] = b.x; Bs[c4 + 1][rr] = b.y;
            Bs[c4 + 2][rr] = b.z; Bs[c4 + 3][rr] = b.w;
        }
        __syncthreads();
        #pragma unroll
        for (int k = 0; k < 16; ++k) {
            float a[8], b[8];
            *(float4*)&a[0] = *(const float4*)&As[k][ty * 8];
            *(float4*)&a[4] = *(const float4*)&As[k][ty * 8 + 4];
            *(float4*)&b[0] = *(const float4*)&Bs[k][tx * 8];
            *(float4*)&b[4] = *(const float4*)&Bs[k][tx * 8 + 4];
            #pragma unroll
            for (int i = 0; i < 8; ++i)
                #pragma unroll
                for (int j = 0; j < 8; ++j) acc[i][j] = fmaf(a[i], b[j], acc[i][j]);
        }
        __syncthreads();
    }
    #pragma unroll
    for (int i = 0; i < 8; ++i) {
        size_t ro = (size_t)(bm + ty * 8 + i) * NI + bn + tx * 8;
        *(float4*)&g_sim[ro]     = make_float4(acc[i][0], acc[i][1], acc[i][2], acc[i][3]);
        *(float4*)&g_sim[ro + 4] = make_float4(acc[i][4], acc[i][5], acc[i][6], acc[i][7]);
    }
    if (bm != bn) {
        #pragma unroll
        for (int j = 0; j < 8; ++j) {
            size_t ro = (size_t)(bn + tx * 8 + j) * NI + bm + ty * 8;
            *(float4*)&g_sim[ro]     = make_float4(acc[0][j], acc[1][j], acc[2][j], acc[3][j]);
            *(float4*)&g_sim[ro + 4] = make_float4(acc[4][j], acc[5][j], acc[6][j], acc[7][j]);
        }
    }
}

// ---------- KNN top-K with cached per-thread argmax; edges to lists ----------
__global__ void __launch_bounds__(256) knn_topk_kernel(int base) {
    int row = blockIdx.x, t = threadIdx.x;
    float v[16];
    const float* srow = g_sim + (size_t)row * NI;
    #pragma unroll
    for (int p = 0; p < 16; ++p) {
        int c = t + p * 256;
        float x = srow[c];
        v[p] = (c == row) ? -INFINITY : x;
    }
    float bv = v[0]; int bp = 0;
    #pragma unroll
    for (int p = 1; p < 16; ++p) if (v[p] > bv) { bv = v[p]; bp = p; }

    __shared__ float swv[8];
    __shared__ int   swi[8];
    __shared__ int   bsel;
    for (int k = 0; k < KNN; ++k) {
        float wv = bv; int wc = t + bp * 256;
        #pragma unroll
        for (int o = 16; o; o >>= 1) {
            float ov = __shfl_xor_sync(0xffffffff, wv, o);
            int   oc = __shfl_xor_sync(0xffffffff, wc, o);
            if (ov > wv || (ov == wv && oc < wc)) { wv = ov; wc = oc; }
        }
        if ((t & 31) == 0) { swv[t >> 5] = wv; swi[t >> 5] = wc; }
        __syncthreads();
        if (t == 0) {
            float BV = swv[0]; int BC = swi[0];
            #pragma unroll
            for (int w = 1; w < 8; ++w)
                if (swv[w] > BV || (swv[w] == BV && swi[w] < BC)) { BV = swv[w]; BC = swi[w]; }
            bsel = BC;
            float wgt = fminf(fmaxf((BV + 1.0f) * 0.5f, 1e-6f), 1.0f);
            int gi = base + row, gj = base + BC;
            int a = atomicAdd(&g_knn_cnt[gi], 1);
            if (a < KCAP) { g_knn_col[(size_t)gi * KCAP + a] = gj; g_knn_w[(size_t)gi * KCAP + a] = wgt; }
            int b = atomicAdd(&g_knn_cnt[gj], 1);
            if (b < KCAP) { g_knn_col[(size_t)gj * KCAP + b] = gi; g_knn_w[(size_t)gj * KCAP + b] = wgt; }
        }
        __syncthreads();
        int sc = bsel;
        if ((sc & 255) == t) {
            v[sc >> 8] = -INFINITY;
            bv = v[0]; bp = 0;
            #pragma unroll
            for (int p = 1; p < 16; ++p) if (v[p] > bv) { bv = v[p]; bp = p; }
        }
    }
}

// ---------- bipartite adjacency lists ----------
__global__ void build_lists_kernel(const float* __restrict__ r) {
    int u = blockIdx.x, t = threadIdx.x;
    __shared__ int scnt;
    if (t == 0) scnt = 0;
    __syncthreads();
    for (int c = t; c < NI; c += 256) {
        if (r[(size_t)u * NI + c] > 0.0f) {
            int p = atomicAdd(&scnt, 1);
            if (p < MAXDEG) g_uitems[u * MAXDEG + p] = c;
            int q = atomicAdd(&g_icnt[c], 1);
            if (q < MAXDEG) g_iusers[c * MAXDEG + q] = u;
        }
    }
    __syncthreads();
    if (t == 0) g_ucnt[u] = scnt;
}

__global__ void invdeg_kernel() {
    int j = blockIdx.x * 256 + threadIdx.x;
    if (j < NN) {
        int c = (j < NU) ? g_ucnt[j] : g_icnt[j - NU];
        g_invdeg[j] = 1.0f / (float)(c + 1);
    }
}

__global__ void zero_piA_kernel() {
    size_t i = (size_t)blockIdx.x * 256 + threadIdx.x;
    float4 z = make_float4(0.f, 0.f, 0.f, 0.f);
    float4* p = (float4*)g_piA;
    size_t total = (size_t)NN * NU / 4;
    for (size_t k = i; k < total; k += (size_t)gridDim.x * 256) p[k] = z;
}

// ---------- build pi2 analytically ----------
__global__ void pi2_build_kernel() {
    int u = blockIdx.x, t = threadIdx.x;
    int lane = t & 31, wid = t >> 5;
    __shared__ int items[MAXDEG];
    __shared__ int du_s;
    if (t == 0) du_s = min(g_ucnt[u], MAXDEG);
    __syncthreads();
    int d = du_s;
    for (int l = t; l < d; l += 256) items[l] = g_uitems[u * MAXDEG + l];
    __syncthreads();
    float duv = g_invdeg[u];
    float v0 = 0.85f * duv + 0.15f;
    float vI = 0.85f * duv;
    if (t == 0) atomicAdd(&g_piA[(size_t)u * NU + u], 0.85f * v0 * duv + 0.15f);
    for (int l = t; l < d; l += 256) {
        int m = NU + items[l];
        atomicAdd(&g_piA[(size_t)m * NU + u], 0.85f * v0 * duv);
    }
    for (int l = wid; l < d; l += 8) {
        int it = items[l];
        float div = g_invdeg[NU + it];
        float add = 0.85f * vI * div;
        if (lane == 0) atomicAdd(&g_piA[(size_t)(NU + it) * NU + u], add);
        int cj = min(g_icnt[it], MAXDEG);
        for (int q = lane; q < cj; q += 32) {
            int up = g_iusers[it * MAXDEG + q];
            atomicAdd(&g_piA[(size_t)up * NU + u], add);
        }
    }
}

// ---------- dense PPR step, u-chunked (1024 columns per launch) ----------
__global__ void __launch_bounds__(256) ppr_step_kernel(int flip, int jbase, int ubase) {
    const float* __restrict__ pin = flip ? g_piB : g_piA;
    float* __restrict__ pout      = flip ? g_piA : g_piB;
    int j = jbase + blockIdx.x;
    int t = threadIdx.x;
    __shared__ int   nbr[MAXDEG];
    __shared__ float nw[MAXDEG];
    __shared__ int   Ls;
    if (t == 0) Ls = min((j < NU) ? g_ucnt[j] : g_icnt[j - NU], MAXDEG);
    __syncthreads();
    int L = Ls;
    if (j < NU) { if (t < L) nbr[t] = NU + g_uitems[j * MAXDEG + t]; }
    else        { if (t < L) nbr[t] = g_iusers[(j - NU) * MAXDEG + t]; }
    __syncthreads();
    if (t < L) nw[t] = g_invdeg[nbr[t]];
    __syncthreads();

    int u0 = ubase + t * 4;
    float dj = g_invdeg[j];
    float4 p = *(const float4*)(pin + (size_t)j * NU + u0);
    float ax = p.x * dj, ay = p.y * dj, az = p.z * dj, aw = p.w * dj;
    for (int l = 0; l < L; ++l) {
        float4 q = *(const float4*)(pin + (size_t)nbr[l] * NU + u0);
        float w = nw[l];
        ax = fmaf(q.x, w, ax); ay = fmaf(q.y, w, ay);
        az = fmaf(q.z, w, az); aw = fmaf(q.w, w, aw);
    }
    ax *= ONEM; ay *= ONEM; az *= ONEM; aw *= ONEM;
    if (j < NU) {
        int du = j - u0;
        if (du == 0) ax += DELTA;
        else if (du == 1) ay += DELTA;
        else if (du == 2) az += DELTA;
        else if (du == 3) aw += DELTA;
    }
    *(float4*)(pout + (size_t)j * NU + u0) = make_float4(ax, ay, az, aw);
}

// ---------- transpose item-block of piB into g_scores[u][it] ----------
__global__ void transpose_scores_kernel() {
    __shared__ float tile[32][33];
    int it0 = blockIdx.x * 32, u0 = blockIdx.y * 32;
    int tx = threadIdx.x, ty = threadIdx.y;
    tile[ty][tx] = g_piB[(size_t)(NU + it0 + ty) * NU + u0 + tx];
    __syncthreads();
    g_scores[(size_t)(u0 + ty) * NI + it0 + tx] = tile[tx][ty];
}

// ---------- mask rated items with -inf (r is binary; positions = uitems) ----------
__global__ void mask_scores_kernel() {
    int u = blockIdx.x, lane = threadIdx.x;
    int d = min(g_ucnt[u], MAXDEG);
    for (int l = lane; l < d; l += 32)
        g_scores[(size_t)u * NI + g_uitems[u * MAXDEG + l]] = -INFINITY;
}

// ---------- PPR top-K -> user-side extra edge lists ----------
__global__ void __launch_bounds__(256) ppr_topk_kernel() {
    int u = blockIdx.x, t = threadIdx.x;
    float v[16];
    const float* srow = g_scores + (size_t)u * NI;
    #pragma unroll
    for (int p = 0; p < 16; ++p) v[p] = srow[t + p * 256];
    float bv = v[0]; int bp = 0;
    #pragma unroll
    for (int p = 1; p < 16; ++p) if (v[p] > bv) { bv = v[p]; bp = p; }

    __shared__ float swv[8];
    __shared__ int   swi[8];
    __shared__ float selv[PPRK];
    __shared__ int   seli[PPRK];
    __shared__ int   bsel;
    for (int k = 0; k < PPRK; ++k) {
        float wv = bv; int wc = t + bp * 256;
        #pragma unroll
        for (int o = 16; o; o >>= 1) {
            float ov = __shfl_xor_sync(0xffffffff, wv, o);
            int   oc = __shfl_xor_sync(0xffffffff, wc, o);
            if (ov > wv || (ov == wv && oc < wc)) { wv = ov; wc = oc; }
        }
        if ((t & 31) == 0) { swv[t >> 5] = wv; swi[t >> 5] = wc; }
        __syncthreads();
        if (t == 0) {
            float BV = swv[0]; int BC = swi[0];
            #pragma unroll
            for (int w = 1; w < 8; ++w)
                if (swv[w] > BV || (swv[w] == BV && swi[w] < BC)) { BV = swv[w]; BC = swi[w]; }
            selv[k] = BV; seli[k] = BC; bsel = BC;
        }
        __syncthreads();
        int sc = bsel;
        if ((sc & 255) == t) {
            v[sc >> 8] = -INFINITY;
            bv = v[0]; bp = 0;
            #pragma unroll
            for (int p = 1; p < 16; ++p) if (v[p] > bv) { bv = v[p]; bp = p; }
        }
    }
    if (t < PPRK) {
        float w  = fmaxf(selv[t], 0.0f);
        float mx = fmaxf(selv[0], 0.0f);
        if (mx > 0.0f) w = w / fmaxf(mx, 1e-12f);
        int it = seli[t];
        g_extra_it[u * PPRK + t] = it;
        g_extra_w[u * PPRK + t]  = w;
        atomicAdd(&g_extra_isum[it], w);
    }
}

// ---------- dedup'd KNN list sums (one warp per node) ----------
__global__ void knn_sum_kernel() {
    int node = blockIdx.x * 8 + (threadIdx.x >> 5);
    int lane = threadIdx.x & 31;
    int c = min(g_knn_cnt[node], KCAP);
    const int*   col = g_knn_col + (size_t)node * KCAP;
    const float* w   = g_knn_w   + (size_t)node * KCAP;
    float s = 0.0f;
    for (int e = lane; e < c; e += 32) {
        int cc = col[e];
        bool dup = false;
        for (int q = 0; q < e; ++q) if (col[q] == cc) { dup = true; break; }
        if (!dup) s += w[e];
    }
    #pragma unroll
    for (int o = 16; o; o >>= 1) s += __shfl_xor_sync(0xffffffff, s, o);
    if (lane == 0) g_knnsum[node] = s;
}

// ---------- total rowsum -> dinv (r sums = counts, since r is binary) ----------
__global__ void dinv_kernel() {
    int i = blockIdx.x * 256 + threadIdx.x;   // 0..8191
    float s = g_knnsum[i];
    if (i < NU) {
        s += (float)g_ucnt[i];
        #pragma unroll
        for (int k = 0; k < PPRK; ++k) s += g_extra_w[i * PPRK + k];
    } else {
        s += (float)g_icnt[i - NU] + g_extra_isum[i - NU];
    }
    g_dinv[i] = (s > 0.0f) ? rsqrtf(fmaxf(s, 1e-12f)) : 0.0f;
}

// ---------- write user rows (full row, scaled; no r read) ----------
__global__ void __launch_bounds__(256) write_user_kernel(float* __restrict__ out) {
    int u = blockIdx.x, t = threadIdx.x;
    __shared__ float bufUU[NU];
    __shared__ float bufUI[NI];
    float4 z = make_float4(0.f, 0.f, 0.f, 0.f);
    #pragma unroll
    for (int q = t; q < NU / 4; q += 256) { ((float4*)bufUU)[q] = z; ((float4*)bufUI)[q] = z; }
    __syncthreads();
    int c = min(g_knn_cnt[u], KCAP);
    for (int l = t; l < c; l += 256) bufUU[g_knn_col[(size_t)u * KCAP + l]] = g_knn_w[(size_t)u * KCAP + l];
    int d = min(g_ucnt[u], MAXDEG);
    for (int l = t; l < d; l += 256) bufUI[g_uitems[u * MAXDEG + l]] = 1.0f;
    if (t < PPRK) bufUI[g_extra_it[u * PPRK + t]] = g_extra_w[u * PPRK + t];
    __syncthreads();
    float du = g_dinv[u];
    size_t rowo = (size_t)u * NN;
    for (int q = t; q < NU / 4; q += 256) {
        float4 b  = ((float4*)bufUU)[q];
        float4 dv = *(const float4*)&g_dinv[q * 4];
        ((float4*)&out[rowo])[q] = make_float4(b.x * du * dv.x, b.y * du * dv.y,
                                               b.z * du * dv.z, b.w * du * dv.w);
    }
    for (int q = t; q < NI / 4; q += 256) {
        float4 b  = ((float4*)bufUI)[q];
        float4 dv = *(const float4*)&g_dinv[NU + q * 4];
        ((float4*)&out[rowo + NU])[q] = make_float4(b.x * du * dv.x, b.y * du * dv.y,
                                                    b.z * du * dv.z, b.w * du * dv.w);
    }
}

// ---------- write item rows (IU from rated users; extras patched after) ----------
__global__ void __launch_bounds__(256) write_item_kernel(float* __restrict__ out) {
    int i = blockIdx.x, t = threadIdx.x;
    int node = NU + i;
    __shared__ float bufIU[NU];
    __shared__ float bufII[NI];
    float4 z = make_float4(0.f, 0.f, 0.f, 0.f);
    #pragma unroll
    for (int q = t; q < NU / 4; q += 256) { ((float4*)bufIU)[q] = z; ((float4*)bufII)[q] = z; }
    __syncthreads();
    int c = min(g_knn_cnt[node], KCAP);
    for (int l = t; l < c; l += 256)
        bufII[g_knn_col[(size_t)node * KCAP + l] - NU] = g_knn_w[(size_t)node * KCAP + l];
    int d = min(g_icnt[i], MAXDEG);
    for (int l = t; l < d; l += 256) bufIU[g_iusers[i * MAXDEG + l]] = 1.0f;
    __syncthreads();
    float dn = g_dinv[node];
    size_t rowo = (size_t)node * NN;
    for (int q = t; q < NU / 4; q += 256) {
        float4 b  = ((float4*)bufIU)[q];
        float4 dv = *(const float4*)&g_dinv[q * 4];
        ((float4*)&out[rowo])[q] = make_float4(b.x * dn * dv.x, b.y * dn * dv.y,
                                               b.z * dn * dv.z, b.w * dn * dv.w);
    }
    for (int q = t; q < NI / 4; q += 256) {
        float4 b  = ((float4*)bufII)[q];
        float4 dv = *(const float4*)&g_dinv[NU + q * 4];
        ((float4*)&out[rowo + NU])[q] = make_float4(b.x * dn * dv.x, b.y * dn * dv.y,
                                                    b.z * dn * dv.z, b.w * dn * dv.w);
    }
}

// ---------- scatter extras into IU quadrant (user-side, uncapped) ----------
__global__ void extra_IU_kernel(float* __restrict__ out) {
    int u = blockIdx.x, t = threadIdx.x;
    if (t < PPRK) {
        int it = g_extra_it[u * PPRK + t];
        float w = g_extra_w[u * PPRK + t];
        out[(size_t)(NU + it) * NN + u] = w * g_dinv[NU + it] * g_dinv[u];
    }
}

// ---------- launch: fork KNN chain onto side stream, join before dinv ----------
extern "C" void kernel_launch(void* const* d_in, const int* in_sizes, int n_in,
                              void* d_out, int out_size) {
    const float* fu = (const float*)d_in[0];
    const float* fi = (const float*)d_in[1];
    const float* r  = (const float*)d_in[2];
    float* out = (float*)d_out;

    static cudaStream_t s2 = 0;
    static cudaEvent_t evF = 0, evJ = 0;
    if (!s2) {
        cudaStreamCreateWithFlags(&s2, cudaStreamNonBlocking);
        cudaEventCreateWithFlags(&evF, cudaEventDisableTiming);
        cudaEventCreateWithFlags(&evJ, cudaEventDisableTiming);
    }

    zero_counts_kernel<<<32, 256>>>();

    // fork: KNN chain on s2 (independent of PPR chain until dinv)
    cudaEventRecord(evF, 0);
    cudaStreamWaitEvent(s2, evF, 0);
    normalize_kernel<<<NN, 128, 0, s2>>>(fu, fi);
    dim3 gs(32, 32);
    syrk_kernel<<<gs, 256, 0, s2>>>(0);
    knn_topk_kernel<<<NU, 256, 0, s2>>>(0);
    syrk_kernel<<<gs, 256, 0, s2>>>(NU);
    knn_topk_kernel<<<NI, 256, 0, s2>>>(NU);
    knn_sum_kernel<<<NN / 8, 256, 0, s2>>>();
    cudaEventRecord(evJ, s2);

    // PPR chain on origin stream
    build_lists_kernel<<<NU, 256>>>(r);
    invdeg_kernel<<<32, 256>>>();
    zero_piA_kernel<<<2048, 256>>>();
    pi2_build_kernel<<<NU, 256>>>();

    for (int c = 0; c < 4; ++c) ppr_step_kernel<<<NN, 256>>>(0, 0, c * 1024);   // pi2->pi3
    for (int c = 0; c < 4; ++c) ppr_step_kernel<<<NN, 256>>>(1, 0, c * 1024);   // pi3->pi4
    for (int c = 0; c < 4; ++c) ppr_step_kernel<<<NI, 256>>>(0, NU, c * 1024);  // pi4->pi5 (items)

    dim3 t32(32, 32);
    transpose_scores_kernel<<<dim3(NI / 32, NU / 32), t32>>>();
    mask_scores_kernel<<<NU, 32>>>();
    ppr_topk_kernel<<<NU, 256>>>();

    // join
    cudaStreamWaitEvent(0, evJ, 0);
    dinv_kernel<<<32, 256>>>();
    write_user_kernel<<<NU, 256>>>(out);
    write_item_kernel<<<NI, 256>>>(out);
    extra_IU_kernel<<<NU, 32>>>(out);
}

// round 12
// speedup vs baseline: 1.9143x; 1.0408x over previous
#include <cuda_runtime.h>
#include <math.h>

#define NU 4096
#define NI 4096
#define NN 8192
#define D  128
#define KNN 10
#define PPRK 20
#define MAXDEG 256
#define KCAP 128
#define DEGCAP 96
#define DELTA 0.15f
#define ONEM  0.85f

// ---------- static device scratch ----------
__device__ float g_xn[(size_t)NN * D];
__device__ float g_sim[(size_t)NU * NI];       // knn chain only
__device__ float g_scores[(size_t)NU * NI];    // ppr chain only
__device__ float g_piA[(size_t)NN * NU];
__device__ float g_piB[(size_t)NN * NU];
__device__ int   g_uitems[NU * MAXDEG];
__device__ int   g_iusers[NI * MAXDEG];
__device__ int   g_ucnt[NU];
__device__ int   g_icnt[NI];
__device__ float g_invdeg[NN];
__device__ float g_dinv[NN];
// knn edge lists (global node ids in col)
__device__ int   g_knn_cnt[NN];
__device__ int   g_knn_col[(size_t)NN * KCAP];
__device__ float g_knn_w[(size_t)NN * KCAP];
__device__ float g_knnsum[NN];
// ppr extra edges (user-side only; item-side is a scatter)
__device__ int   g_extra_it[NU * PPRK];
__device__ float g_extra_w[NU * PPRK];
__device__ float g_extra_isum[NI];

// ---------- zero all counters ----------
__global__ void zero_counts_kernel() {
    int i = blockIdx.x * 256 + threadIdx.x;   // 0..8191
    g_knn_cnt[i] = 0;
    if (i < NU) g_ucnt[i] = 0;
    if (i < NI) {
        g_icnt[i] = 0;
        g_extra_isum[i] = 0.0f;
    }
}

// ---------- row-normalize features ----------
__global__ void normalize_kernel(const float* __restrict__ fu, const float* __restrict__ fi) {
    int row = blockIdx.x;
    int t = threadIdx.x; // 128 threads
    const float* src = (row < NU) ? &fu[(size_t)row * D] : &fi[(size_t)(row - NU) * D];
    float v = src[t];
    float s = v * v;
    #pragma unroll
    for (int o = 16; o; o >>= 1) s += __shfl_xor_sync(0xffffffff, s, o);
    __shared__ float ws[4];
    if ((t & 31) == 0) ws[t >> 5] = s;
    __syncthreads();
    float tot = ws[0] + ws[1] + ws[2] + ws[3];
    g_xn[(size_t)row * D + t] = v / fmaxf(sqrtf(tot), 1e-12f);
}

// ---------- SYRK: sim = Xn Xn^T (streaming stores; don't pollute L2) ----------
__global__ void __launch_bounds__(256) syrk_kernel(int base) {
    int bm = blockIdx.y * 128, bn = blockIdx.x * 128;
    if (bn < bm) return;
    __shared__ float As[16][132];
    __shared__ float Bs[16][132];
    int tid = threadIdx.x;
    int tx = tid & 15, ty = tid >> 4;
    const float* X = g_xn + (size_t)base * D;
    float acc[8][8] = {};
    for (int k0 = 0; k0 < D; k0 += 16) {
        #pragma unroll
        for (int l = 0; l < 2; ++l) {
            int idx = tid * 2 + l;
            int rr  = idx >> 2;
            int c4  = (idx & 3) * 4;
            float4 a = *(const float4*)&X[(size_t)(bm + rr) * D + k0 + c4];
            As[c4 + 0][rr] = a.x; As[c4 + 1][rr] = a.y;
            As[c4 + 2][rr] = a.z; As[c4 + 3][rr] = a.w;
            float4 b = *(const float4*)&X[(size_t)(bn + rr) * D + k0 + c4];
            Bs[c4 + 0][rr] = b.x; Bs[c4 + 1][rr] = b.y;
            Bs[c4 + 2][rr] = b.z; Bs[c4 + 3][rr] = b.w;
        }
        __syncthreads();
        #pragma unroll
        for (int k = 0; k < 16; ++k) {
            float a[8], b[8];
            *(float4*)&a[0] = *(const float4*)&As[k][ty * 8];
            *(float4*)&a[4] = *(const float4*)&As[k][ty * 8 + 4];
            *(float4*)&b[0] = *(const float4*)&Bs[k][tx * 8];
            *(float4*)&b[4] = *(const float4*)&Bs[k][tx * 8 + 4];
            #pragma unroll
            for (int i = 0; i < 8; ++i)
                #pragma unroll
                for (int j = 0; j < 8; ++j) acc[i][j] = fmaf(a[i], b[j], acc[i][j]);
        }
        __syncthreads();
    }
    #pragma unroll
    for (int i = 0; i < 8; ++i) {
        size_t ro = (size_t)(bm + ty * 8 + i) * NI + bn + tx * 8;
        __stcs((float4*)&g_sim[ro],     make_float4(acc[i][0], acc[i][1], acc[i][2], acc[i][3]));
        __stcs((float4*)&g_sim[ro + 4], make_float4(acc[i][4], acc[i][5], acc[i][6], acc[i][7]));
    }
    if (bm != bn) {
        #pragma unroll
        for (int j = 0; j < 8; ++j) {
            size_t ro = (size_t)(bn + tx * 8 + j) * NI + bm + ty * 8;
            __stcs((float4*)&g_sim[ro],     make_float4(acc[0][j], acc[1][j], acc[2][j], acc[3][j]));
            __stcs((float4*)&g_sim[ro + 4], make_float4(acc[4][j], acc[5][j], acc[6][j], acc[7][j]));
        }
    }
}

// ---------- KNN top-K with cached per-thread argmax; edges to lists ----------
__global__ void __launch_bounds__(256) knn_topk_kernel(int base) {
    int row = blockIdx.x, t = threadIdx.x;
    float v[16];
    const float* srow = g_sim + (size_t)row * NI;
    #pragma unroll
    for (int p = 0; p < 16; ++p) {
        int c = t + p * 256;
        float x = __ldcs(&srow[c]);
        v[p] = (c == row) ? -INFINITY : x;
    }
    float bv = v[0]; int bp = 0;
    #pragma unroll
    for (int p = 1; p < 16; ++p) if (v[p] > bv) { bv = v[p]; bp = p; }

    __shared__ float swv[8];
    __shared__ int   swi[8];
    __shared__ int   bsel;
    for (int k = 0; k < KNN; ++k) {
        float wv = bv; int wc = t + bp * 256;
        #pragma unroll
        for (int o = 16; o; o >>= 1) {
            float ov = __shfl_xor_sync(0xffffffff, wv, o);
            int   oc = __shfl_xor_sync(0xffffffff, wc, o);
            if (ov > wv || (ov == wv && oc < wc)) { wv = ov; wc = oc; }
        }
        if ((t & 31) == 0) { swv[t >> 5] = wv; swi[t >> 5] = wc; }
        __syncthreads();
        if (t == 0) {
            float BV = swv[0]; int BC = swi[0];
            #pragma unroll
            for (int w = 1; w < 8; ++w)
                if (swv[w] > BV || (swv[w] == BV && swi[w] < BC)) { BV = swv[w]; BC = swi[w]; }
            bsel = BC;
            float wgt = fminf(fmaxf((BV + 1.0f) * 0.5f, 1e-6f), 1.0f);
            int gi = base + row, gj = base + BC;
            int a = atomicAdd(&g_knn_cnt[gi], 1);
            if (a < KCAP) { g_knn_col[(size_t)gi * KCAP + a] = gj; g_knn_w[(size_t)gi * KCAP + a] = wgt; }
            int b = atomicAdd(&g_knn_cnt[gj], 1);
            if (b < KCAP) { g_knn_col[(size_t)gj * KCAP + b] = gi; g_knn_w[(size_t)gj * KCAP + b] = wgt; }
        }
        __syncthreads();
        int sc = bsel;
        if ((sc & 255) == t) {
            v[sc >> 8] = -INFINITY;
            bv = v[0]; bp = 0;
            #pragma unroll
            for (int p = 1; p < 16; ++p) if (v[p] > bv) { bv = v[p]; bp = p; }
        }
    }
}

// ---------- bipartite adjacency lists ----------
__global__ void build_lists_kernel(const float* __restrict__ r) {
    int u = blockIdx.x, t = threadIdx.x;
    __shared__ int scnt;
    if (t == 0) scnt = 0;
    __syncthreads();
    for (int c = t; c < NI; c += 256) {
        if (__ldcs(&r[(size_t)u * NI + c]) > 0.0f) {
            int p = atomicAdd(&scnt, 1);
            if (p < MAXDEG) g_uitems[u * MAXDEG + p] = c;
            int q = atomicAdd(&g_icnt[c], 1);
            if (q < MAXDEG) g_iusers[c * MAXDEG + q] = u;
        }
    }
    __syncthreads();
    if (t == 0) g_ucnt[u] = scnt;
}

__global__ void invdeg_kernel() {
    int j = blockIdx.x * 256 + threadIdx.x;
    if (j < NN) {
        int c = (j < NU) ? g_ucnt[j] : g_icnt[j - NU];
        g_invdeg[j] = 1.0f / (float)(c + 1);
    }
}

__global__ void zero_piA_kernel() {
    size_t i = (size_t)blockIdx.x * 256 + threadIdx.x;
    float4 z = make_float4(0.f, 0.f, 0.f, 0.f);
    float4* p = (float4*)g_piA;
    size_t total = (size_t)NN * NU / 4;
    for (size_t k = i; k < total; k += (size_t)gridDim.x * 256) p[k] = z;
}

// ---------- build pi2 analytically ----------
__global__ void pi2_build_kernel() {
    int u = blockIdx.x, t = threadIdx.x;
    int lane = t & 31, wid = t >> 5;
    __shared__ int items[MAXDEG];
    __shared__ int du_s;
    if (t == 0) du_s = min(g_ucnt[u], MAXDEG);
    __syncthreads();
    int d = du_s;
    for (int l = t; l < d; l += 256) items[l] = g_uitems[u * MAXDEG + l];
    __syncthreads();
    float duv = g_invdeg[u];
    float v0 = 0.85f * duv + 0.15f;
    float vI = 0.85f * duv;
    if (t == 0) atomicAdd(&g_piA[(size_t)u * NU + u], 0.85f * v0 * duv + 0.15f);
    for (int l = t; l < d; l += 256) {
        int m = NU + items[l];
        atomicAdd(&g_piA[(size_t)m * NU + u], 0.85f * v0 * duv);
    }
    for (int l = wid; l < d; l += 8) {
        int it = items[l];
        float div = g_invdeg[NU + it];
        float add = 0.85f * vI * div;
        if (lane == 0) atomicAdd(&g_piA[(size_t)(NU + it) * NU + u], add);
        int cj = min(g_icnt[it], MAXDEG);
        for (int q = lane; q < cj; q += 32) {
            int up = g_iusers[it * MAXDEG + q];
            atomicAdd(&g_piA[(size_t)up * NU + u], add);
        }
    }
}

// ---------- dense PPR step, u-chunked (1024 columns per launch) ----------
__global__ void __launch_bounds__(256) ppr_step_kernel(int flip, int jbase, int ubase) {
    const float* __restrict__ pin = flip ? g_piB : g_piA;
    float* __restrict__ pout      = flip ? g_piA : g_piB;
    int j = jbase + blockIdx.x;
    int t = threadIdx.x;
    __shared__ int   nbr[MAXDEG];
    __shared__ float nw[MAXDEG];
    __shared__ int   Ls;
    if (t == 0) Ls = min((j < NU) ? g_ucnt[j] : g_icnt[j - NU], MAXDEG);
    __syncthreads();
    int L = Ls;
    if (j < NU) { if (t < L) nbr[t] = NU + g_uitems[j * MAXDEG + t]; }
    else        { if (t < L) nbr[t] = g_iusers[(j - NU) * MAXDEG + t]; }
    __syncthreads();
    if (t < L) nw[t] = g_invdeg[nbr[t]];
    __syncthreads();

    int u0 = ubase + t * 4;
    float dj = g_invdeg[j];
    float4 p = *(const float4*)(pin + (size_t)j * NU + u0);
    float ax = p.x * dj, ay = p.y * dj, az = p.z * dj, aw = p.w * dj;
    for (int l = 0; l < L; ++l) {
        float4 q = *(const float4*)(pin + (size_t)nbr[l] * NU + u0);
        float w = nw[l];
        ax = fmaf(q.x, w, ax); ay = fmaf(q.y, w, ay);
        az = fmaf(q.z, w, az); aw = fmaf(q.w, w, aw);
    }
    ax *= ONEM; ay *= ONEM; az *= ONEM; aw *= ONEM;
    if (j < NU) {
        int du = j - u0;
        if (du == 0) ax += DELTA;
        else if (du == 1) ay += DELTA;
        else if (du == 2) az += DELTA;
        else if (du == 3) aw += DELTA;
    }
    *(float4*)(pout + (size_t)j * NU + u0) = make_float4(ax, ay, az, aw);
}

// ---------- fused final PPR step (item rows) + transpose into g_scores[u][it] ----------
// grid: (NI/32, NU/128), block 256. Reads pi4 from g_piA; per-element FMA order
// identical to ppr_step_kernel so values are bit-identical to the unfused version.
__global__ void __launch_bounds__(256) ppr_item_T_kernel() {
    int i0 = blockIdx.x * 32;     // item tile
    int u0 = blockIdx.y * 128;    // user-column tile
    int t = threadIdx.x;
    int w = t >> 5, lane = t & 31;
    __shared__ int   sdeg[32];
    __shared__ int   snbr[32][DEGCAP];
    __shared__ float snw[32][DEGCAP];
    __shared__ float stile[32][132];   // [j-within-tile][u-within-tile]
    if (t < 32) sdeg[t] = min(g_icnt[i0 + t], DEGCAP);
    __syncthreads();
    for (int idx = t; idx < 32 * DEGCAP; idx += 256) {
        int rr = idx / DEGCAP, l = idx - rr * DEGCAP;
        if (l < sdeg[rr]) {
            int up = g_iusers[(i0 + rr) * MAXDEG + l];
            snbr[rr][l] = up;
            snw[rr][l]  = g_invdeg[up];
        }
    }
    __syncthreads();
    const float* __restrict__ pin = g_piA;
    for (int rr = w; rr < 32; rr += 8) {
        int j = NU + i0 + rr;
        float dj = g_invdeg[j];
        float4 p = *(const float4*)(pin + (size_t)j * NU + u0 + lane * 4);
        float ax = p.x * dj, ay = p.y * dj, az = p.z * dj, aw = p.w * dj;
        int L = sdeg[rr];
        for (int l = 0; l < L; ++l) {
            float4 q = *(const float4*)(pin + (size_t)snbr[rr][l] * NU + u0 + lane * 4);
            float wl = snw[rr][l];
            ax = fmaf(q.x, wl, ax); ay = fmaf(q.y, wl, ay);
            az = fmaf(q.z, wl, az); aw = fmaf(q.w, wl, aw);
        }
        stile[rr][lane * 4 + 0] = ax * ONEM;
        stile[rr][lane * 4 + 1] = ay * ONEM;
        stile[rr][lane * 4 + 2] = az * ONEM;
        stile[rr][lane * 4 + 3] = aw * ONEM;
    }
    __syncthreads();
    // write transposed: g_scores[u0+ur][i0 + part*16 .. +15]
    int ur = t >> 1, part = t & 1;
    float vals[16];
    #pragma unroll
    for (int c = 0; c < 16; ++c) vals[c] = stile[part * 16 + c][ur];
    float4* dst = (float4*)(g_scores + (size_t)(u0 + ur) * NI + i0 + part * 16);
    dst[0] = make_float4(vals[0], vals[1], vals[2], vals[3]);
    dst[1] = make_float4(vals[4], vals[5], vals[6], vals[7]);
    dst[2] = make_float4(vals[8], vals[9], vals[10], vals[11]);
    dst[3] = make_float4(vals[12], vals[13], vals[14], vals[15]);
}

// ---------- mask rated items with -inf (r is binary; positions = uitems) ----------
__global__ void mask_scores_kernel() {
    int u = blockIdx.x, lane = threadIdx.x;
    int d = min(g_ucnt[u], MAXDEG);
    for (int l = lane; l < d; l += 32)
        g_scores[(size_t)u * NI + g_uitems[u * MAXDEG + l]] = -INFINITY;
}

// ---------- PPR top-K -> user-side extra edge lists ----------
__global__ void __launch_bounds__(256) ppr_topk_kernel() {
    int u = blockIdx.x, t = threadIdx.x;
    float v[16];
    const float* srow = g_scores + (size_t)u * NI;
    #pragma unroll
    for (int p = 0; p < 16; ++p) v[p] = srow[t + p * 256];
    float bv = v[0]; int bp = 0;
    #pragma unroll
    for (int p = 1; p < 16; ++p) if (v[p] > bv) { bv = v[p]; bp = p; }

    __shared__ float swv[8];
    __shared__ int   swi[8];
    __shared__ float selv[PPRK];
    __shared__ int   seli[PPRK];
    __shared__ int   bsel;
    for (int k = 0; k < PPRK; ++k) {
        float wv = bv; int wc = t + bp * 256;
        #pragma unroll
        for (int o = 16; o; o >>= 1) {
            float ov = __shfl_xor_sync(0xffffffff, wv, o);
            int   oc = __shfl_xor_sync(0xffffffff, wc, o);
            if (ov > wv || (ov == wv && oc < wc)) { wv = ov; wc = oc; }
        }
        if ((t & 31) == 0) { swv[t >> 5] = wv; swi[t >> 5] = wc; }
        __syncthreads();
        if (t == 0) {
            float BV = swv[0]; int BC = swi[0];
            #pragma unroll
            for (int w = 1; w < 8; ++w)
                if (swv[w] > BV || (swv[w] == BV && swi[w] < BC)) { BV = swv[w]; BC = swi[w]; }
            selv[k] = BV; seli[k] = BC; bsel = BC;
        }
        __syncthreads();
        int sc = bsel;
        if ((sc & 255) == t) {
            v[sc >> 8] = -INFINITY;
            bv = v[0]; bp = 0;
            #pragma unroll
            for (int p = 1; p < 16; ++p) if (v[p] > bv) { bv = v[p]; bp = p; }
        }
    }
    if (t < PPRK) {
        float w  = fmaxf(selv[t], 0.0f);
        float mx = fmaxf(selv[0], 0.0f);
        if (mx > 0.0f) w = w / fmaxf(mx, 1e-12f);
        int it = seli[t];
        g_extra_it[u * PPRK + t] = it;
        g_extra_w[u * PPRK + t]  = w;
        atomicAdd(&g_extra_isum[it], w);
    }
}

// ---------- dedup'd KNN list sums (one warp per node) ----------
__global__ void knn_sum_kernel() {
    int node = blockIdx.x * 8 + (threadIdx.x >> 5);
    int lane = threadIdx.x & 31;
    int c = min(g_knn_cnt[node], KCAP);
    const int*   col = g_knn_col + (size_t)node * KCAP;
    const float* w   = g_knn_w   + (size_t)node * KCAP;
    float s = 0.0f;
    for (int e = lane; e < c; e += 32) {
        int cc = col[e];
        bool dup = false;
        for (int q = 0; q < e; ++q) if (col[q] == cc) { dup = true; break; }
        if (!dup) s += w[e];
    }
    #pragma unroll
    for (int o = 16; o; o >>= 1) s += __shfl_xor_sync(0xffffffff, s, o);
    if (lane == 0) g_knnsum[node] = s;
}

// ---------- total rowsum -> dinv (r sums = counts, since r is binary) ----------
__global__ void dinv_kernel() {
    int i = blockIdx.x * 256 + threadIdx.x;   // 0..8191
    float s = g_knnsum[i];
    if (i < NU) {
        s += (float)g_ucnt[i];
        #pragma unroll
        for (int k = 0; k < PPRK; ++k) s += g_extra_w[i * PPRK + k];
    } else {
        s += (float)g_icnt[i - NU] + g_extra_isum[i - NU];
    }
    g_dinv[i] = (s > 0.0f) ? rsqrtf(fmaxf(s, 1e-12f)) : 0.0f;
}

// ---------- write user rows (full row, scaled; no r read) ----------
__global__ void __launch_bounds__(256) write_user_kernel(float* __restrict__ out) {
    int u = blockIdx.x, t = threadIdx.x;
    __shared__ float bufUU[NU];
    __shared__ float bufUI[NI];
    float4 z = make_float4(0.f, 0.f, 0.f, 0.f);
    #pragma unroll
    for (int q = t; q < NU / 4; q += 256) { ((float4*)bufUU)[q] = z; ((float4*)bufUI)[q] = z; }
    __syncthreads();
    int c = min(g_knn_cnt[u], KCAP);
    for (int l = t; l < c; l += 256) bufUU[g_knn_col[(size_t)u * KCAP + l]] = g_knn_w[(size_t)u * KCAP + l];
    int d = min(g_ucnt[u], MAXDEG);
    for (int l = t; l < d; l += 256) bufUI[g_uitems[u * MAXDEG + l]] = 1.0f;
    if (t < PPRK) bufUI[g_extra_it[u * PPRK + t]] = g_extra_w[u * PPRK + t];
    __syncthreads();
    float du = g_dinv[u];
    size_t rowo = (size_t)u * NN;
    for (int q = t; q < NU / 4; q += 256) {
        float4 b  = ((float4*)bufUU)[q];
        float4 dv = *(const float4*)&g_dinv[q * 4];
        ((float4*)&out[rowo])[q] = make_float4(b.x * du * dv.x, b.y * du * dv.y,
                                               b.z * du * dv.z, b.w * du * dv.w);
    }
    for (int q = t; q < NI / 4; q += 256) {
        float4 b  = ((float4*)bufUI)[q];
        float4 dv = *(const float4*)&g_dinv[NU + q * 4];
        ((float4*)&out[rowo + NU])[q] = make_float4(b.x * du * dv.x, b.y * du * dv.y,
                                                    b.z * du * dv.z, b.w * du * dv.w);
    }
}

// ---------- write item rows (IU from rated users; extras patched after) ----------
__global__ void __launch_bounds__(256) write_item_kernel(float* __restrict__ out) {
    int i = blockIdx.x, t = threadIdx.x;
    int node = NU + i;
    __shared__ float bufIU[NU];
    __shared__ float bufII[NI];
    float4 z = make_float4(0.f, 0.f, 0.f, 0.f);
    #pragma unroll
    for (int q = t; q < NU / 4; q += 256) { ((float4*)bufIU)[q] = z; ((float4*)bufII)[q] = z; }
    __syncthreads();
    int c = min(g_knn_cnt[node], KCAP);
    for (int l = t; l < c; l += 256)
        bufII[g_knn_col[(size_t)node * KCAP + l] - NU] = g_knn_w[(size_t)node * KCAP + l];
    int d = min(g_icnt[i], MAXDEG);
    for (int l = t; l < d; l += 256) bufIU[g_iusers[i * MAXDEG + l]] = 1.0f;
    __syncthreads();
    float dn = g_dinv[node];
    size_t rowo = (size_t)node * NN;
    for (int q = t; q < NU / 4; q += 256) {
        float4 b  = ((float4*)bufIU)[q];
        float4 dv = *(const float4*)&g_dinv[q * 4];
        ((float4*)&out[rowo])[q] = make_float4(b.x * dn * dv.x, b.y * dn * dv.y,
                                               b.z * dn * dv.z, b.w * dn * dv.w);
    }
    for (int q = t; q < NI / 4; q += 256) {
        float4 b  = ((float4*)bufII)[q];
        float4 dv = *(const float4*)&g_dinv[NU + q * 4];
        ((float4*)&out[rowo + NU])[q] = make_float4(b.x * dn * dv.x, b.y * dn * dv.y,
                                                    b.z * dn * dv.z, b.w * dn * dv.w);
    }
}

// ---------- scatter extras into IU quadrant (user-side, uncapped) ----------
__global__ void extra_IU_kernel(float* __restrict__ out) {
    int u = blockIdx.x, t = threadIdx.x;
    if (t < PPRK) {
        int it = g_extra_it[u * PPRK + t];
        float w = g_extra_w[u * PPRK + t];
        out[(size_t)(NU + it) * NN + u] = w * g_dinv[NU + it] * g_dinv[u];
    }
}

// ---------- launch: fork KNN chain (+zero_piA) onto side stream ----------
extern "C" void kernel_launch(void* const* d_in, const int* in_sizes, int n_in,
                              void* d_out, int out_size) {
    const float* fu = (const float*)d_in[0];
    const float* fi = (const float*)d_in[1];
    const float* r  = (const float*)d_in[2];
    float* out = (float*)d_out;

    static cudaStream_t s2 = 0;
    static cudaEvent_t evF = 0, evZ = 0, evJ = 0;
    if (!s2) {
        cudaStreamCreateWithFlags(&s2, cudaStreamNonBlocking);
        cudaEventCreateWithFlags(&evF, cudaEventDisableTiming);
        cudaEventCreateWithFlags(&evZ, cudaEventDisableTiming);
        cudaEventCreateWithFlags(&evJ, cudaEventDisableTiming);
    }

    zero_counts_kernel<<<32, 256>>>();

    // fork: zero_piA + KNN chain on s2
    cudaEventRecord(evF, 0);
    cudaStreamWaitEvent(s2, evF, 0);
    zero_piA_kernel<<<2048, 256, 0, s2>>>();
    cudaEventRecord(evZ, s2);
    normalize_kernel<<<NN, 128, 0, s2>>>(fu, fi);
    dim3 gs(32, 32);
    syrk_kernel<<<gs, 256, 0, s2>>>(0);
    knn_topk_kernel<<<NU, 256, 0, s2>>>(0);
    syrk_kernel<<<gs, 256, 0, s2>>>(NU);
    knn_topk_kernel<<<NI, 256, 0, s2>>>(NU);
    knn_sum_kernel<<<NN / 8, 256, 0, s2>>>();
    cudaEventRecord(evJ, s2);

    // PPR chain on origin stream
    build_lists_kernel<<<NU, 256>>>(r);
    invdeg_kernel<<<32, 256>>>();
    cudaStreamWaitEvent(0, evZ, 0);
    pi2_build_kernel<<<NU, 256>>>();

    for (int c = 0; c < 4; ++c) ppr_step_kernel<<<NN, 256>>>(0, 0, c * 1024);   // pi2->pi3
    for (int c = 0; c < 4; ++c) ppr_step_kernel<<<NN, 256>>>(1, 0, c * 1024);   // pi3->pi4
    ppr_item_T_kernel<<<dim3(NI / 32, NU / 128), 256>>>();                      // pi4->pi5 fused + T

    mask_scores_kernel<<<NU, 32>>>();
    ppr_topk_kernel<<<NU, 256>>>();

    // join
    cudaStreamWaitEvent(0, evJ, 0);
    dinv_kernel<<<32, 256>>>();
    write_user_kernel<<<NU, 256>>>(out);
    write_item_kernel<<<NI, 256>>>(out);
    extra_IU_kernel<<<NU, 32>>>(out);
}

// round 13
// speedup vs baseline: 1.9512x; 1.0193x over previous
#include <cuda_runtime.h>
#include <math.h>

#define NU 4096
#define NI 4096
#define NN 8192
#define D  128
#define KNN 10
#define PPRK 20
#define MAXDEG 256
#define KCAP 128
#define DEGCAP 96
#define DELTA 0.15f
#define ONEM  0.85f

// ---------- static device scratch ----------
__device__ float g_xn[(size_t)NN * D];
__device__ float g_sim[(size_t)NU * NI];       // knn chain only
__device__ float g_scores[(size_t)NU * NI];    // ppr chain only
__device__ float g_piA[(size_t)NN * NU];
__device__ float g_piB[(size_t)NN * NU];
__device__ int   g_uitems[NU * MAXDEG];
__device__ int   g_iusers[NI * MAXDEG];
__device__ int   g_ucnt[NU];
__device__ int   g_icnt[NI];
__device__ float g_invdeg[NN];
__device__ float g_dinv[NN];
// knn edge lists (global node ids in col)
__device__ int   g_knn_cnt[NN];
__device__ int   g_knn_col[(size_t)NN * KCAP];
__device__ float g_knn_w[(size_t)NN * KCAP];
__device__ float g_knnsum[NN];
// ppr extra edges (user-side only; item-side is a scatter)
__device__ int   g_extra_it[NU * PPRK];
__device__ float g_extra_w[NU * PPRK];
__device__ float g_extra_isum[NI];

// ---------- zero all counters ----------
__global__ void zero_counts_kernel() {
    int i = blockIdx.x * 256 + threadIdx.x;   // 0..8191
    g_knn_cnt[i] = 0;
    if (i < NU) g_ucnt[i] = 0;
    if (i < NI) {
        g_icnt[i] = 0;
        g_extra_isum[i] = 0.0f;
    }
}

// ---------- row-normalize features ----------
__global__ void normalize_kernel(const float* __restrict__ fu, const float* __restrict__ fi) {
    int row = blockIdx.x;
    int t = threadIdx.x; // 128 threads
    const float* src = (row < NU) ? &fu[(size_t)row * D] : &fi[(size_t)(row - NU) * D];
    float v = src[t];
    float s = v * v;
    #pragma unroll
    for (int o = 16; o; o >>= 1) s += __shfl_xor_sync(0xffffffff, s, o);
    __shared__ float ws[4];
    if ((t & 31) == 0) ws[t >> 5] = s;
    __syncthreads();
    float tot = ws[0] + ws[1] + ws[2] + ws[3];
    g_xn[(size_t)row * D + t] = v / fmaxf(sqrtf(tot), 1e-12f);
}

// ---------- SYRK: sim = Xn Xn^T (streaming stores; don't pollute L2) ----------
__global__ void __launch_bounds__(256) syrk_kernel(int base) {
    int bm = blockIdx.y * 128, bn = blockIdx.x * 128;
    if (bn < bm) return;
    __shared__ float As[16][132];
    __shared__ float Bs[16][132];
    int tid = threadIdx.x;
    int tx = tid & 15, ty = tid >> 4;
    const float* X = g_xn + (size_t)base * D;
    float acc[8][8] = {};
    for (int k0 = 0; k0 < D; k0 += 16) {
        #pragma unroll
        for (int l = 0; l < 2; ++l) {
            int idx = tid * 2 + l;
            int rr  = idx >> 2;
            int c4  = (idx & 3) * 4;
            float4 a = *(const float4*)&X[(size_t)(bm + rr) * D + k0 + c4];
            As[c4 + 0][rr] = a.x; As[c4 + 1][rr] = a.y;
            As[c4 + 2][rr] = a.z; As[c4 + 3][rr] = a.w;
            float4 b = *(const float4*)&X[(size_t)(bn + rr) * D + k0 + c4];
            Bs[c4 + 0][rr] = b.x; Bs[c4 + 1][rr] = b.y;
            Bs[c4 + 2][rr] = b.z; Bs[c4 + 3][rr] = b.w;
        }
        __syncthreads();
        #pragma unroll
        for (int k = 0; k < 16; ++k) {
            float a[8], b[8];
            *(float4*)&a[0] = *(const float4*)&As[k][ty * 8];
            *(float4*)&a[4] = *(const float4*)&As[k][ty * 8 + 4];
            *(float4*)&b[0] = *(const float4*)&Bs[k][tx * 8];
            *(float4*)&b[4] = *(const float4*)&Bs[k][tx * 8 + 4];
            #pragma unroll
            for (int i = 0; i < 8; ++i)
                #pragma unroll
                for (int j = 0; j < 8; ++j) acc[i][j] = fmaf(a[i], b[j], acc[i][j]);
        }
        __syncthreads();
    }
    #pragma unroll
    for (int i = 0; i < 8; ++i) {
        size_t ro = (size_t)(bm + ty * 8 + i) * NI + bn + tx * 8;
        __stcs((float4*)&g_sim[ro],     make_float4(acc[i][0], acc[i][1], acc[i][2], acc[i][3]));
        __stcs((float4*)&g_sim[ro + 4], make_float4(acc[i][4], acc[i][5], acc[i][6], acc[i][7]));
    }
    if (bm != bn) {
        #pragma unroll
        for (int j = 0; j < 8; ++j) {
            size_t ro = (size_t)(bn + tx * 8 + j) * NI + bm + ty * 8;
            __stcs((float4*)&g_sim[ro],     make_float4(acc[0][j], acc[1][j], acc[2][j], acc[3][j]));
            __stcs((float4*)&g_sim[ro + 4], make_float4(acc[4][j], acc[5][j], acc[6][j], acc[7][j]));
        }
    }
}

// ---------- KNN top-K with cached per-thread argmax; edges to lists ----------
__global__ void __launch_bounds__(256) knn_topk_kernel(int base) {
    int row = blockIdx.x, t = threadIdx.x;
    float v[16];
    const float* srow = g_sim + (size_t)row * NI;
    #pragma unroll
    for (int p = 0; p < 16; ++p) {
        int c = t + p * 256;
        float x = __ldcs(&srow[c]);
        v[p] = (c == row) ? -INFINITY : x;
    }
    float bv = v[0]; int bp = 0;
    #pragma unroll
    for (int p = 1; p < 16; ++p) if (v[p] > bv) { bv = v[p]; bp = p; }

    __shared__ float swv[8];
    __shared__ int   swi[8];
    __shared__ int   bsel;
    for (int k = 0; k < KNN; ++k) {
        float wv = bv; int wc = t + bp * 256;
        #pragma unroll
        for (int o = 16; o; o >>= 1) {
            float ov = __shfl_xor_sync(0xffffffff, wv, o);
            int   oc = __shfl_xor_sync(0xffffffff, wc, o);
            if (ov > wv || (ov == wv && oc < wc)) { wv = ov; wc = oc; }
        }
        if ((t & 31) == 0) { swv[t >> 5] = wv; swi[t >> 5] = wc; }
        __syncthreads();
        if (t == 0) {
            float BV = swv[0]; int BC = swi[0];
            #pragma unroll
            for (int w = 1; w < 8; ++w)
                if (swv[w] > BV || (swv[w] == BV && swi[w] < BC)) { BV = swv[w]; BC = swi[w]; }
            bsel = BC;
            float wgt = fminf(fmaxf((BV + 1.0f) * 0.5f, 1e-6f), 1.0f);
            int gi = base + row, gj = base + BC;
            int a = atomicAdd(&g_knn_cnt[gi], 1);
            if (a < KCAP) { g_knn_col[(size_t)gi * KCAP + a] = gj; g_knn_w[(size_t)gi * KCAP + a] = wgt; }
            int b = atomicAdd(&g_knn_cnt[gj], 1);
            if (b < KCAP) { g_knn_col[(size_t)gj * KCAP + b] = gi; g_knn_w[(size_t)gj * KCAP + b] = wgt; }
        }
        __syncthreads();
        int sc = bsel;
        if ((sc & 255) == t) {
            v[sc >> 8] = -INFINITY;
            bv = v[0]; bp = 0;
            #pragma unroll
            for (int p = 1; p < 16; ++p) if (v[p] > bv) { bv = v[p]; bp = p; }
        }
    }
}

// ---------- bipartite adjacency lists (float4 reads) ----------
__global__ void build_lists_kernel(const float* __restrict__ r) {
    int u = blockIdx.x, t = threadIdx.x;
    __shared__ int scnt;
    if (t == 0) scnt = 0;
    __syncthreads();
    const float4* rr = (const float4*)(r + (size_t)u * NI);
    for (int c4 = t; c4 < NI / 4; c4 += 256) {
        float4 x = __ldcs(&rr[c4]);
        #pragma unroll
        for (int b = 0; b < 4; ++b) {
            float xv = (b == 0) ? x.x : (b == 1) ? x.y : (b == 2) ? x.z : x.w;
            if (xv > 0.0f) {
                int c = c4 * 4 + b;
                int p = atomicAdd(&scnt, 1);
                if (p < MAXDEG) g_uitems[u * MAXDEG + p] = c;
                int q = atomicAdd(&g_icnt[c], 1);
                if (q < MAXDEG) g_iusers[c * MAXDEG + q] = u;
            }
        }
    }
    __syncthreads();
    if (t == 0) g_ucnt[u] = scnt;
}

__global__ void invdeg_kernel() {
    int j = blockIdx.x * 256 + threadIdx.x;
    if (j < NN) {
        int c = (j < NU) ? g_ucnt[j] : g_icnt[j - NU];
        g_invdeg[j] = 1.0f / (float)(c + 1);
    }
}

__global__ void zero_piA_kernel() {
    size_t i = (size_t)blockIdx.x * 256 + threadIdx.x;
    float4 z = make_float4(0.f, 0.f, 0.f, 0.f);
    float4* p = (float4*)g_piA;
    size_t total = (size_t)NN * NU / 4;
    for (size_t k = i; k < total; k += (size_t)gridDim.x * 256) p[k] = z;
}

// ---------- build pi2 analytically ----------
__global__ void pi2_build_kernel() {
    int u = blockIdx.x, t = threadIdx.x;
    int lane = t & 31, wid = t >> 5;
    __shared__ int items[MAXDEG];
    __shared__ int du_s;
    if (t == 0) du_s = min(g_ucnt[u], MAXDEG);
    __syncthreads();
    int d = du_s;
    for (int l = t; l < d; l += 256) items[l] = g_uitems[u * MAXDEG + l];
    __syncthreads();
    float duv = g_invdeg[u];
    float v0 = 0.85f * duv + 0.15f;
    float vI = 0.85f * duv;
    if (t == 0) atomicAdd(&g_piA[(size_t)u * NU + u], 0.85f * v0 * duv + 0.15f);
    for (int l = t; l < d; l += 256) {
        int m = NU + items[l];
        atomicAdd(&g_piA[(size_t)m * NU + u], 0.85f * v0 * duv);
    }
    for (int l = wid; l < d; l += 8) {
        int it = items[l];
        float div = g_invdeg[NU + it];
        float add = 0.85f * vI * div;
        if (lane == 0) atomicAdd(&g_piA[(size_t)(NU + it) * NU + u], add);
        int cj = min(g_icnt[it], MAXDEG);
        for (int q = lane; q < cj; q += 32) {
            int up = g_iusers[it * MAXDEG + q];
            atomicAdd(&g_piA[(size_t)up * NU + u], add);
        }
    }
}

// ---------- dense PPR step, u-chunked (1024 columns per launch) ----------
__global__ void __launch_bounds__(256) ppr_step_kernel(int flip, int jbase, int ubase) {
    const float* __restrict__ pin = flip ? g_piB : g_piA;
    float* __restrict__ pout      = flip ? g_piA : g_piB;
    int j = jbase + blockIdx.x;
    int t = threadIdx.x;
    __shared__ int   nbr[MAXDEG];
    __shared__ float nw[MAXDEG];
    __shared__ int   Ls;
    if (t == 0) Ls = min((j < NU) ? g_ucnt[j] : g_icnt[j - NU], MAXDEG);
    __syncthreads();
    int L = Ls;
    if (j < NU) { if (t < L) nbr[t] = NU + g_uitems[j * MAXDEG + t]; }
    else        { if (t < L) nbr[t] = g_iusers[(j - NU) * MAXDEG + t]; }
    __syncthreads();
    if (t < L) nw[t] = g_invdeg[nbr[t]];
    __syncthreads();

    int u0 = ubase + t * 4;
    float dj = g_invdeg[j];
    float4 p = *(const float4*)(pin + (size_t)j * NU + u0);
    float ax = p.x * dj, ay = p.y * dj, az = p.z * dj, aw = p.w * dj;
    for (int l = 0; l < L; ++l) {
        float4 q = *(const float4*)(pin + (size_t)nbr[l] * NU + u0);
        float w = nw[l];
        ax = fmaf(q.x, w, ax); ay = fmaf(q.y, w, ay);
        az = fmaf(q.z, w, az); aw = fmaf(q.w, w, aw);
    }
    ax *= ONEM; ay *= ONEM; az *= ONEM; aw *= ONEM;
    if (j < NU) {
        int du = j - u0;
        if (du == 0) ax += DELTA;
        else if (du == 1) ay += DELTA;
        else if (du == 2) az += DELTA;
        else if (du == 3) aw += DELTA;
    }
    *(float4*)(pout + (size_t)j * NU + u0) = make_float4(ax, ay, az, aw);
}

// ---------- fused final PPR step (item rows) + in-tile mask + transpose ----------
// grid: (NI/32, NU/128), block 256. Reads pi4 from g_piA. Per-element FMA order
// identical to ppr_step_kernel; rated (u,item) cells set to -inf before store.
__global__ void __launch_bounds__(256) ppr_item_T_kernel() {
    int i0 = blockIdx.x * 32;     // item tile
    int u0 = blockIdx.y * 128;    // user-column tile
    int t = threadIdx.x;
    int w = t >> 5, lane = t & 31;
    __shared__ int   sdeg[32];
    __shared__ int   snbr[32][DEGCAP];
    __shared__ float snw[32][DEGCAP];
    __shared__ float stile[32][132];   // [item-within-tile][u-within-tile]
    if (t < 32) sdeg[t] = min(g_icnt[i0 + t], DEGCAP);
    __syncthreads();
    for (int idx = t; idx < 32 * DEGCAP; idx += 256) {
        int rr = idx / DEGCAP, l = idx - rr * DEGCAP;
        if (l < sdeg[rr]) {
            int up = g_iusers[(i0 + rr) * MAXDEG + l];
            snbr[rr][l] = up;
            snw[rr][l]  = g_invdeg[up];
        }
    }
    __syncthreads();
    const float* __restrict__ pin = g_piA;
    for (int rr = w; rr < 32; rr += 8) {
        int j = NU + i0 + rr;
        float dj = g_invdeg[j];
        float4 p = *(const float4*)(pin + (size_t)j * NU + u0 + lane * 4);
        float ax = p.x * dj, ay = p.y * dj, az = p.z * dj, aw = p.w * dj;
        int L = sdeg[rr];
        for (int l = 0; l < L; ++l) {
            float4 q = *(const float4*)(pin + (size_t)snbr[rr][l] * NU + u0 + lane * 4);
            float wl = snw[rr][l];
            ax = fmaf(q.x, wl, ax); ay = fmaf(q.y, wl, ay);
            az = fmaf(q.z, wl, az); aw = fmaf(q.w, wl, aw);
        }
        stile[rr][lane * 4 + 0] = ax * ONEM;
        stile[rr][lane * 4 + 1] = ay * ONEM;
        stile[rr][lane * 4 + 2] = az * ONEM;
        stile[rr][lane * 4 + 3] = aw * ONEM;
    }
    __syncthreads();
    // in-tile mask: rated (u, item) -> -inf. Each warp w handles items w, w+8, ...
    for (int rr = w; rr < 32; rr += 8) {
        int L = sdeg[rr];
        for (int l = lane; l < L; l += 32) {
            int up = snbr[rr][l];
            int du = up - u0;
            if (du >= 0 && du < 128) stile[rr][du] = -INFINITY;
        }
    }
    __syncthreads();
    // write transposed: g_scores[u0+ur][i0 + part*16 .. +15]
    int ur = t >> 1, part = t & 1;
    float vals[16];
    #pragma unroll
    for (int c = 0; c < 16; ++c) vals[c] = stile[part * 16 + c][ur];
    float4* dst = (float4*)(g_scores + (size_t)(u0 + ur) * NI + i0 + part * 16);
    dst[0] = make_float4(vals[0], vals[1], vals[2], vals[3]);
    dst[1] = make_float4(vals[4], vals[5], vals[6], vals[7]);
    dst[2] = make_float4(vals[8], vals[9], vals[10], vals[11]);
    dst[3] = make_float4(vals[12], vals[13], vals[14], vals[15]);
}

// ---------- PPR top-K -> user-side extra edge lists ----------
__global__ void __launch_bounds__(256) ppr_topk_kernel() {
    int u = blockIdx.x, t = threadIdx.x;
    float v[16];
    const float* srow = g_scores + (size_t)u * NI;
    #pragma unroll
    for (int p = 0; p < 16; ++p) v[p] = srow[t + p * 256];
    float bv = v[0]; int bp = 0;
    #pragma unroll
    for (int p = 1; p < 16; ++p) if (v[p] > bv) { bv = v[p]; bp = p; }

    __shared__ float swv[8];
    __shared__ int   swi[8];
    __shared__ float selv[PPRK];
    __shared__ int   seli[PPRK];
    __shared__ int   bsel;
    for (int k = 0; k < PPRK; ++k) {
        float wv = bv; int wc = t + bp * 256;
        #pragma unroll
        for (int o = 16; o; o >>= 1) {
            float ov = __shfl_xor_sync(0xffffffff, wv, o);
            int   oc = __shfl_xor_sync(0xffffffff, wc, o);
            if (ov > wv || (ov == wv && oc < wc)) { wv = ov; wc = oc; }
        }
        if ((t & 31) == 0) { swv[t >> 5] = wv; swi[t >> 5] = wc; }
        __syncthreads();
        if (t == 0) {
            float BV = swv[0]; int BC = swi[0];
            #pragma unroll
            for (int w = 1; w < 8; ++w)
                if (swv[w] > BV || (swv[w] == BV && swi[w] < BC)) { BV = swv[w]; BC = swi[w]; }
            selv[k] = BV; seli[k] = BC; bsel = BC;
        }
        __syncthreads();
        int sc = bsel;
        if ((sc & 255) == t) {
            v[sc >> 8] = -INFINITY;
            bv = v[0]; bp = 0;
            #pragma unroll
            for (int p = 1; p < 16; ++p) if (v[p] > bv) { bv = v[p]; bp = p; }
        }
    }
    if (t < PPRK) {
        float w  = fmaxf(selv[t], 0.0f);
        float mx = fmaxf(selv[0], 0.0f);
        if (mx > 0.0f) w = w / fmaxf(mx, 1e-12f);
        int it = seli[t];
        g_extra_it[u * PPRK + t] = it;
        g_extra_w[u * PPRK + t]  = w;
        atomicAdd(&g_extra_isum[it], w);
    }
}

// ---------- dedup'd KNN list sums (one warp per node) ----------
__global__ void knn_sum_kernel() {
    int node = blockIdx.x * 8 + (threadIdx.x >> 5);
    int lane = threadIdx.x & 31;
    int c = min(g_knn_cnt[node], KCAP);
    const int*   col = g_knn_col + (size_t)node * KCAP;
    const float* w   = g_knn_w   + (size_t)node * KCAP;
    float s = 0.0f;
    for (int e = lane; e < c; e += 32) {
        int cc = col[e];
        bool dup = false;
        for (int q = 0; q < e; ++q) if (col[q] == cc) { dup = true; break; }
        if (!dup) s += w[e];
    }
    #pragma unroll
    for (int o = 16; o; o >>= 1) s += __shfl_xor_sync(0xffffffff, s, o);
    if (lane == 0) g_knnsum[node] = s;
}

// ---------- total rowsum -> dinv (r sums = counts, since r is binary) ----------
__global__ void dinv_kernel() {
    int i = blockIdx.x * 256 + threadIdx.x;   // 0..8191
    float s = g_knnsum[i];
    if (i < NU) {
        s += (float)g_ucnt[i];
        #pragma unroll
        for (int k = 0; k < PPRK; ++k) s += g_extra_w[i * PPRK + k];
    } else {
        s += (float)g_icnt[i - NU] + g_extra_isum[i - NU];
    }
    g_dinv[i] = (s > 0.0f) ? rsqrtf(fmaxf(s, 1e-12f)) : 0.0f;
}

// ---------- write user rows (full row, scaled; no r read) ----------
__global__ void __launch_bounds__(256) write_user_kernel(float* __restrict__ out) {
    int u = blockIdx.x, t = threadIdx.x;
    __shared__ float bufUU[NU];
    __shared__ float bufUI[NI];
    float4 z = make_float4(0.f, 0.f, 0.f, 0.f);
    #pragma unroll
    for (int q = t; q < NU / 4; q += 256) { ((float4*)bufUU)[q] = z; ((float4*)bufUI)[q] = z; }
    __syncthreads();
    int c = min(g_knn_cnt[u], KCAP);
    for (int l = t; l < c; l += 256) bufUU[g_knn_col[(size_t)u * KCAP + l]] = g_knn_w[(size_t)u * KCAP + l];
    int d = min(g_ucnt[u], MAXDEG);
    for (int l = t; l < d; l += 256) bufUI[g_uitems[u * MAXDEG + l]] = 1.0f;
    if (t < PPRK) bufUI[g_extra_it[u * PPRK + t]] = g_extra_w[u * PPRK + t];
    __syncthreads();
    float du = g_dinv[u];
    size_t rowo = (size_t)u * NN;
    for (int q = t; q < NU / 4; q += 256) {
        float4 b  = ((float4*)bufUU)[q];
        float4 dv = *(const float4*)&g_dinv[q * 4];
        ((float4*)&out[rowo])[q] = make_float4(b.x * du * dv.x, b.y * du * dv.y,
                                               b.z * du * dv.z, b.w * du * dv.w);
    }
    for (int q = t; q < NI / 4; q += 256) {
        float4 b  = ((float4*)bufUI)[q];
        float4 dv = *(const float4*)&g_dinv[NU + q * 4];
        ((float4*)&out[rowo + NU])[q] = make_float4(b.x * du * dv.x, b.y * du * dv.y,
                                                    b.z * du * dv.z, b.w * du * dv.w);
    }
}

// ---------- write item rows (IU from rated users; extras patched after) ----------
__global__ void __launch_bounds__(256) write_item_kernel(float* __restrict__ out) {
    int i = blockIdx.x, t = threadIdx.x;
    int node = NU + i;
    __shared__ float bufIU[NU];
    __shared__ float bufII[NI];
    float4 z = make_float4(0.f, 0.f, 0.f, 0.f);
    #pragma unroll
    for (int q = t; q < NU / 4; q += 256) { ((float4*)bufIU)[q] = z; ((float4*)bufII)[q] = z; }
    __syncthreads();
    int c = min(g_knn_cnt[node], KCAP);
    for (int l = t; l < c; l += 256)
        bufII[g_knn_col[(size_t)node * KCAP + l] - NU] = g_knn_w[(size_t)node * KCAP + l];
    int d = min(g_icnt[i], MAXDEG);
    for (int l = t; l < d; l += 256) bufIU[g_iusers[i * MAXDEG + l]] = 1.0f;
    __syncthreads();
    float dn = g_dinv[node];
    size_t rowo = (size_t)node * NN;
    for (int q = t; q < NU / 4; q += 256) {
        float4 b  = ((float4*)bufIU)[q];
        float4 dv = *(const float4*)&g_dinv[q * 4];
        ((float4*)&out[rowo])[q] = make_float4(b.x * dn * dv.x, b.y * dn * dv.y,
                                               b.z * dn * dv.z, b.w * dn * dv.w);
    }
    for (int q = t; q < NI / 4; q += 256) {
        float4 b  = ((float4*)bufII)[q];
        float4 dv = *(const float4*)&g_dinv[NU + q * 4];
        ((float4*)&out[rowo + NU])[q] = make_float4(b.x * dn * dv.x, b.y * dn * dv.y,
                                                    b.z * dn * dv.z, b.w * dn * dv.w);
    }
}

// ---------- scatter extras into IU quadrant (user-side, uncapped) ----------
__global__ void extra_IU_kernel(float* __restrict__ out) {
    int u = blockIdx.x, t = threadIdx.x;
    if (t < PPRK) {
        int it = g_extra_it[u * PPRK + t];
        float w = g_extra_w[u * PPRK + t];
        out[(size_t)(NU + it) * NN + u] = w * g_dinv[NU + it] * g_dinv[u];
    }
}

// ---------- launch ----------
extern "C" void kernel_launch(void* const* d_in, const int* in_sizes, int n_in,
                              void* d_out, int out_size) {
    const float* fu = (const float*)d_in[0];
    const float* fi = (const float*)d_in[1];
    const float* r  = (const float*)d_in[2];
    float* out = (float*)d_out;

    static cudaStream_t s2 = 0;
    static cudaEvent_t evF = 0, evZ = 0, evJ = 0, evD = 0, evJ2 = 0;
    if (!s2) {
        cudaStreamCreateWithFlags(&s2, cudaStreamNonBlocking);
        cudaEventCreateWithFlags(&evF, cudaEventDisableTiming);
        cudaEventCreateWithFlags(&evZ, cudaEventDisableTiming);
        cudaEventCreateWithFlags(&evJ, cudaEventDisableTiming);
        cudaEventCreateWithFlags(&evD, cudaEventDisableTiming);
        cudaEventCreateWithFlags(&evJ2, cudaEventDisableTiming);
    }

    zero_counts_kernel<<<32, 256>>>();

    // fork: zero_piA + KNN chain on s2
    cudaEventRecord(evF, 0);
    cudaStreamWaitEvent(s2, evF, 0);
    zero_piA_kernel<<<2048, 256, 0, s2>>>();
    cudaEventRecord(evZ, s2);
    normalize_kernel<<<NN, 128, 0, s2>>>(fu, fi);
    dim3 gs(32, 32);
    syrk_kernel<<<gs, 256, 0, s2>>>(0);
    knn_topk_kernel<<<NU, 256, 0, s2>>>(0);
    syrk_kernel<<<gs, 256, 0, s2>>>(NU);
    knn_topk_kernel<<<NI, 256, 0, s2>>>(NU);
    knn_sum_kernel<<<NN / 8, 256, 0, s2>>>();
    cudaEventRecord(evJ, s2);

    // PPR chain on origin stream
    build_lists_kernel<<<NU, 256>>>(r);
    invdeg_kernel<<<32, 256>>>();
    cudaStreamWaitEvent(0, evZ, 0);
    pi2_build_kernel<<<NU, 256>>>();

    for (int c = 0; c < 4; ++c) ppr_step_kernel<<<NN, 256>>>(0, 0, c * 1024);   // pi2->pi3
    for (int c = 0; c < 4; ++c) ppr_step_kernel<<<NN, 256>>>(1, 0, c * 1024);   // pi3->pi4
    ppr_item_T_kernel<<<dim3(NI / 32, NU / 128), 256>>>();                      // pi4->pi5 fused + mask + T

    ppr_topk_kernel<<<NU, 256>>>();

    // join knn chain, compute dinv
    cudaStreamWaitEvent(0, evJ, 0);
    dinv_kernel<<<32, 256>>>();
    cudaEventRecord(evD, 0);

    // parallel tail: user rows on main, item rows on s2
    cudaStreamWaitEvent(s2, evD, 0);
    write_item_kernel<<<NI, 256, 0, s2>>>(out);
    extra_IU_kernel<<<NU, 32, 0, s2>>>(out);
    cudaEventRecord(evJ2, s2);

    write_user_kernel<<<NU, 256>>>(out);
    cudaStreamWaitEvent(0, evJ2, 0);
}